// round 3
// baseline (speedup 1.0000x reference)
#include <cuda_runtime.h>
#include <math.h>

#define ACT_NONE 0
#define ACT_RELU 1
#define ACT_SIG  2

#define BM 128
#define BN 128
#define BKC 8

// ---------------- scratch (one __device__ symbol, no allocation) ----------------
// layout (floats):
//  m2 20480000 | m3 5120000 | m4 1280000 | m5 320000
//  p2 20480000 | p3 5120000 | p4 1280000 | p5 320000 | p6 86528
//  r  40960000 | pooled 131072 | fc1 524288 | fc2 524288
#define SC_M2     0L
#define SC_M3     (SC_M2 + 20480000L)
#define SC_M4     (SC_M3 + 5120000L)
#define SC_M5     (SC_M4 + 1280000L)
#define SC_P2     (SC_M5 + 320000L)
#define SC_P3     (SC_P2 + 20480000L)
#define SC_P4     (SC_P3 + 5120000L)
#define SC_P5     (SC_P4 + 1280000L)
#define SC_P6     (SC_P5 + 320000L)
#define SC_R      (SC_P6 + 86528L)
#define SC_POOL   (SC_R + 40960000L)
#define SC_FC1    (SC_POOL + 131072L)
#define SC_FC2    (SC_FC1 + 524288L)
#define SC_TOTAL  (SC_FC2 + 524288L)

__device__ __align__(16) float g_scratch[SC_TOTAL];

// ---------------- output offsets (reference tuple flattened) ----------------
#define OFF_CLS2 0L
#define OFF_CLS3 240000L
#define OFF_CLS4 300000L
#define OFF_CLS5 315000L
#define OFF_CLS6 318750L
#define OFF_REG2 319764L
#define OFF_REG3 1279764L
#define OFF_REG4 1519764L
#define OFF_REG5 1579764L
#define OFF_REG6 1594764L
#define OFF_ROICLS 1598820L
#define OFF_ROIREG 1602916L
#define OFF_ANCH   1619300L

// ---------------- implicit-GEMM conv ----------------
struct ConvParams {
    const float* __restrict__ in;
    const float* __restrict__ w;
    const float* __restrict__ bias;
    float* __restrict__ out;
    int Hin, Win, logCin;
    int Hout, Wout, Cout;
    int M;          // Nb*Hout*Wout
    int KW, stride, pad, Ktot, act;
};

__global__ __launch_bounds__(256) void conv_gemm(ConvParams p) {
    __shared__ float As[BKC][BM];
    __shared__ float Bs[BKC][BN];
    const int tid = threadIdx.x;
    const int m0 = blockIdx.x * BM;
    const int n0 = blockIdx.y * BN;

    // A-tile load assignment: 128 rows x 8 k, float4 per thread
    const int arow = tid >> 1;
    const int kq = (tid & 1) << 2;
    const int am = m0 + arow;
    const bool am_ok = am < p.M;
    int aoh = 0, aow = 0;
    const float* abase = p.in;
    if (am_ok) {
        int hw = p.Hout * p.Wout;
        int an = am / hw;
        int r = am - an * hw;
        aoh = r / p.Wout;
        aow = r - aoh * p.Wout;
        abase = p.in + (((long)an * p.Hin * p.Win) << p.logCin);
    }
    // B-tile load: 8 k x 128 n, float4 per thread
    const int brow = tid >> 5;
    const int bcol = (tid & 31) << 2;
    const bool bvec = ((p.Cout & 3) == 0) && (n0 + BN <= p.Cout);
    const int cmask = (1 << p.logCin) - 1;

    float acc[8][8];
#pragma unroll
    for (int i = 0; i < 8; i++)
#pragma unroll
        for (int j = 0; j < 8; j++) acc[i][j] = 0.f;

    const int ty = tid >> 4, tx = tid & 15;

    for (int kb = 0; kb < p.Ktot; kb += BKC) {
        float4 av = make_float4(0.f, 0.f, 0.f, 0.f);
        if (am_ok) {
            int k0 = kb + kq;
            int tap = k0 >> p.logCin;
            int ci = k0 & cmask;
            int dy = tap / p.KW;
            int dx = tap - dy * p.KW;
            int ih = aoh * p.stride + dy - p.pad;
            int iw = aow * p.stride + dx - p.pad;
            if ((unsigned)ih < (unsigned)p.Hin && (unsigned)iw < (unsigned)p.Win) {
                av = *reinterpret_cast<const float4*>(
                    abase + (((long)ih * p.Win + iw) << p.logCin) + ci);
            }
        }
        As[kq + 0][arow] = av.x;
        As[kq + 1][arow] = av.y;
        As[kq + 2][arow] = av.z;
        As[kq + 3][arow] = av.w;

        {
            int kB = kb + brow;
            const float* wp = p.w + (long)kB * p.Cout + n0 + bcol;
            float4 bv;
            if (bvec) {
                bv = *reinterpret_cast<const float4*>(wp);
            } else {
                int nb = n0 + bcol;
                bv.x = (nb + 0 < p.Cout) ? wp[0] : 0.f;
                bv.y = (nb + 1 < p.Cout) ? wp[1] : 0.f;
                bv.z = (nb + 2 < p.Cout) ? wp[2] : 0.f;
                bv.w = (nb + 3 < p.Cout) ? wp[3] : 0.f;
            }
            *reinterpret_cast<float4*>(&Bs[brow][bcol]) = bv;
        }

        __syncthreads();
#pragma unroll
        for (int kk = 0; kk < BKC; kk++) {
            float4 a0 = *reinterpret_cast<const float4*>(&As[kk][ty << 3]);
            float4 a1 = *reinterpret_cast<const float4*>(&As[kk][(ty << 3) + 4]);
            float4 b0 = *reinterpret_cast<const float4*>(&Bs[kk][tx << 3]);
            float4 b1 = *reinterpret_cast<const float4*>(&Bs[kk][(tx << 3) + 4]);
            float ra[8] = {a0.x, a0.y, a0.z, a0.w, a1.x, a1.y, a1.z, a1.w};
            float rb[8] = {b0.x, b0.y, b0.z, b0.w, b1.x, b1.y, b1.z, b1.w};
#pragma unroll
            for (int i = 0; i < 8; i++)
#pragma unroll
                for (int j = 0; j < 8; j++)
                    acc[i][j] += ra[i] * rb[j];
        }
        __syncthreads();
    }

#pragma unroll
    for (int i = 0; i < 8; i++) {
        int m = m0 + (ty << 3) + i;
        if (m >= p.M) continue;
#pragma unroll
        for (int j = 0; j < 8; j++) {
            int n = n0 + (tx << 3) + j;
            if (n >= p.Cout) continue;
            float v = acc[i][j] + p.bias[n];
            if (p.act == ACT_RELU) v = fmaxf(v, 0.f);
            else if (p.act == ACT_SIG) v = 1.f / (1.f + expf(-v));
            p.out[(long)m * p.Cout + n] = v;
        }
    }
}

// ---------------- FPN top-down add: dst += up2(src) ----------------
__global__ void up2_add_kernel(float* __restrict__ dst, const float* __restrict__ src,
                               int H, int W, int C, int total) {
    int i = blockIdx.x * blockDim.x + threadIdx.x;
    if (i >= total) return;
    int c = i & (C - 1);
    int t = i >> 8;            // C == 256
    int w = t % W; t /= W;
    int h = t % H; int n = t / H;
    int Hs = H >> 1, Ws = W >> 1;
    dst[i] += src[((((long)n * Hs + (h >> 1)) * Ws + (w >> 1)) << 8) + c];
}

// ---------------- crop_and_resize(7x7, bilinear) + mean pool ----------------
__global__ void roi_pool_kernel(const float* __restrict__ fm, const float* __restrict__ rois,
                                float* __restrict__ pooled) {
    int roi = blockIdx.x;
    int c = threadIdx.x;   // 256 channels
    __shared__ int sy0[7], sy1[7], sx0[7], sx1[7];
    __shared__ float swy[7], swx[7];
    __shared__ int svy[7], svx[7];
    if (c == 0) {
        float y1 = rois[roi * 4 + 0] / 50.0f;
        float x1 = rois[roi * 4 + 1] / 50.0f;
        float y2 = rois[roi * 4 + 2] / 50.0f;
        float x2 = rois[roi * 4 + 3] / 50.0f;
        for (int i = 0; i < 7; i++) {
            float ys = y1 * 49.0f + (float)i * ((y2 - y1) * 49.0f / 6.0f);
            float xs = x1 * 49.0f + (float)i * ((x2 - x1) * 49.0f / 6.0f);
            float fy = floorf(ys), fx = floorf(xs);
            int iy0 = min(max((int)fy, 0), 49);
            int ix0 = min(max((int)fx, 0), 49);
            sy0[i] = iy0; sy1[i] = min(iy0 + 1, 49);
            sx0[i] = ix0; sx1[i] = min(ix0 + 1, 49);
            swy[i] = ys - fy; swx[i] = xs - fx;
            svy[i] = (ys >= 0.0f && ys <= 49.0f);
            svx[i] = (xs >= 0.0f && xs <= 49.0f);
        }
    }
    __syncthreads();
    float acc = 0.f;
    for (int iy = 0; iy < 7; iy++) {
        if (!svy[iy]) continue;
        float wy = swy[iy];
        const float* r0 = fm + ((long)sy0[iy] * 50 << 8);
        const float* r1 = fm + ((long)sy1[iy] * 50 << 8);
        for (int ix = 0; ix < 7; ix++) {
            if (!svx[ix]) continue;
            float wx = swx[ix];
            float v00 = r0[(sx0[ix] << 8) + c];
            float v01 = r0[(sx1[ix] << 8) + c];
            float v10 = r1[(sx0[ix] << 8) + c];
            float v11 = r1[(sx1[ix] << 8) + c];
            acc += (1.f - wy) * (1.f - wx) * v00 + (1.f - wy) * wx * v01 +
                   wy * (1.f - wx) * v10 + wy * wx * v11;
        }
    }
    pooled[(roi << 8) + c] = acc * (1.0f / 49.0f);
}

// ---------------- softmax over 8 classes, in place ----------------
__global__ void softmax8_kernel(float* __restrict__ x) {
    int r = blockIdx.x * blockDim.x + threadIdx.x;
    if (r >= 512) return;
    float* p = x + r * 8;
    float m = p[0];
#pragma unroll
    for (int i = 1; i < 8; i++) m = fmaxf(m, p[i]);
    float e[8], s = 0.f;
#pragma unroll
    for (int i = 0; i < 8; i++) { e[i] = expf(p[i] - m); s += e[i]; }
    float inv = 1.0f / s;
#pragma unroll
    for (int i = 0; i < 8; i++) p[i] = e[i] * inv;
}

// ---------------- anchors ----------------
__global__ void anchors_kernel(float* __restrict__ out) {
    int idx = blockIdx.x * blockDim.x + threadIdx.x;
    if (idx >= 159882) return;
    int lvl, a;
    if (idx < 120000)      { lvl = 0; a = idx; }
    else if (idx < 150000) { lvl = 1; a = idx - 120000; }
    else if (idx < 157500) { lvl = 2; a = idx - 150000; }
    else if (idx < 159375) { lvl = 3; a = idx - 157500; }
    else                   { lvl = 4; a = idx - 159375; }
    const int   ws[5]  = {200, 100, 50, 25, 13};
    const float scl[5] = {32.f, 64.f, 128.f, 256.f, 512.f};
    const float st[5]  = {4.f, 8.f, 16.f, 32.f, 64.f};
    const float sq[3]  = {0.70710678118654752f, 1.0f, 1.41421356237309505f};
    int r = a % 3;
    int cell = a / 3;
    int w = ws[lvl];
    int y = cell / w, x = cell - y * w;
    float sx = (float)x * st[lvl], sy = (float)y * st[lvl];
    float s = scl[lvl];
    float hx = s * sq[r] * 0.5f;
    float hy = s / sq[r] * 0.5f;
    out[idx * 4 + 0] = sx - hx;
    out[idx * 4 + 1] = sy - hy;
    out[idx * 4 + 2] = sx + hx;
    out[idx * 4 + 3] = sy + hy;
}

// ---------------- host side ----------------
static void run_conv(const float* in, const float* w, const float* b, float* out,
                     int Nb, int Hin, int Win, int logCin,
                     int Hout, int Wout, int Cout,
                     int KW, int KH, int stride, int pad, int act) {
    ConvParams p;
    p.in = in; p.w = w; p.bias = b; p.out = out;
    p.Hin = Hin; p.Win = Win; p.logCin = logCin;
    p.Hout = Hout; p.Wout = Wout; p.Cout = Cout;
    p.M = Nb * Hout * Wout;
    p.KW = KW; p.stride = stride; p.pad = pad;
    p.Ktot = (KH * KW) << logCin;
    p.act = act;
    dim3 grid((p.M + BM - 1) / BM, (Cout + BN - 1) / BN);
    conv_gemm<<<grid, 256>>>(p);
}

extern "C" void kernel_launch(void* const* d_in, const int* in_sizes, int n_in,
                              void* d_out, int out_size) {
    const float* feat2 = (const float*)d_in[0];
    const float* feat3 = (const float*)d_in[1];
    const float* feat4 = (const float*)d_in[2];
    const float* feat5 = (const float*)d_in[3];
    const float* rois  = (const float*)d_in[4];
    const float* lw2 = (const float*)d_in[5];  const float* lb2 = (const float*)d_in[6];
    const float* lw3 = (const float*)d_in[7];  const float* lb3 = (const float*)d_in[8];
    const float* lw4 = (const float*)d_in[9];  const float* lb4 = (const float*)d_in[10];
    const float* lw5 = (const float*)d_in[11]; const float* lb5 = (const float*)d_in[12];
    const float* fw  = (const float*)d_in[13]; const float* fb  = (const float*)d_in[14];
    const float* p6w = (const float*)d_in[15]; const float* p6b = (const float*)d_in[16];
    const float* rpnw = (const float*)d_in[17]; const float* rpnb = (const float*)d_in[18];
    const float* clsw = (const float*)d_in[19]; const float* clsb = (const float*)d_in[20];
    const float* regw = (const float*)d_in[21]; const float* regb = (const float*)d_in[22];
    const float* fc1w = (const float*)d_in[23]; const float* fc1b = (const float*)d_in[24];
    const float* fc2w = (const float*)d_in[25]; const float* fc2b = (const float*)d_in[26];
    const float* hclsw = (const float*)d_in[27]; const float* hclsb = (const float*)d_in[28];
    const float* hregw = (const float*)d_in[29]; const float* hregb = (const float*)d_in[30];
    float* out = (float*)d_out;

    float* sc = nullptr;
    cudaGetSymbolAddress((void**)&sc, g_scratch);
    float* m2 = sc + SC_M2;  float* m3 = sc + SC_M3;
    float* m4 = sc + SC_M4;  float* m5 = sc + SC_M5;
    float* p2 = sc + SC_P2;  float* p3 = sc + SC_P3;
    float* p4 = sc + SC_P4;  float* p5 = sc + SC_P5;
    float* p6 = sc + SC_P6;  float* rbuf = sc + SC_R;
    float* pooled = sc + SC_POOL;
    float* fc1 = sc + SC_FC1; float* fc2 = sc + SC_FC2;

    // ---- laterals (1x1) + top-down ----
    run_conv(feat5, lw5, lb5, m5, 2, 25, 25, 11, 25, 25, 256, 1, 1, 1, 0, ACT_NONE);
    run_conv(feat4, lw4, lb4, m4, 2, 50, 50, 10, 50, 50, 256, 1, 1, 1, 0, ACT_NONE);
    {
        int tot = 2 * 50 * 50 * 256;
        up2_add_kernel<<<(tot + 255) / 256, 256>>>(m4, m5, 50, 50, 256, tot);
    }
    run_conv(feat3, lw3, lb3, m3, 2, 100, 100, 9, 100, 100, 256, 1, 1, 1, 0, ACT_NONE);
    {
        int tot = 2 * 100 * 100 * 256;
        up2_add_kernel<<<(tot + 255) / 256, 256>>>(m3, m4, 100, 100, 256, tot);
    }
    run_conv(feat2, lw2, lb2, m2, 2, 200, 200, 8, 200, 200, 256, 1, 1, 1, 0, ACT_NONE);
    {
        int tot = 2 * 200 * 200 * 256;
        up2_add_kernel<<<(tot + 255) / 256, 256>>>(m2, m3, 200, 200, 256, tot);
    }

    // ---- FPN 3x3 smoothing convs ----
    run_conv(m2, fw + 0L * 589824, fb + 0,   p2, 2, 200, 200, 8, 200, 200, 256, 3, 3, 1, 1, ACT_NONE);
    run_conv(m3, fw + 1L * 589824, fb + 256, p3, 2, 100, 100, 8, 100, 100, 256, 3, 3, 1, 1, ACT_NONE);
    run_conv(m4, fw + 2L * 589824, fb + 512, p4, 2, 50, 50, 8, 50, 50, 256, 3, 3, 1, 1, ACT_NONE);
    run_conv(m5, fw + 3L * 589824, fb + 768, p5, 2, 25, 25, 8, 25, 25, 256, 3, 3, 1, 1, ACT_NONE);
    run_conv(p5, p6w, p6b, p6, 2, 25, 25, 8, 13, 13, 256, 3, 3, 2, 1, ACT_NONE);

    // ---- RPN heads per level ----
    struct Lv { const float* f; int H, W; long co, ro; };
    Lv lv[5] = {
        {p2, 200, 200, OFF_CLS2, OFF_REG2},
        {p3, 100, 100, OFF_CLS3, OFF_REG3},
        {p4,  50,  50, OFF_CLS4, OFF_REG4},
        {p5,  25,  25, OFF_CLS5, OFF_REG5},
        {p6,  13,  13, OFF_CLS6, OFF_REG6},
    };
    for (int i = 0; i < 5; i++) {
        run_conv(lv[i].f, rpnw, rpnb, rbuf, 2, lv[i].H, lv[i].W, 8,
                 lv[i].H, lv[i].W, 512, 3, 3, 1, 1, ACT_RELU);
        run_conv(rbuf, clsw, clsb, out + lv[i].co, 2, lv[i].H, lv[i].W, 9,
                 lv[i].H, lv[i].W, 3, 1, 1, 1, 0, ACT_SIG);
        run_conv(rbuf, regw, regb, out + lv[i].ro, 2, lv[i].H, lv[i].W, 9,
                 lv[i].H, lv[i].W, 12, 1, 1, 1, 0, ACT_NONE);
    }

    // ---- RoI head ----
    roi_pool_kernel<<<512, 256>>>(p4, rois, pooled);  // batch 0 of p4
    run_conv(pooled, fc1w, fc1b, fc1, 1, 512, 1, 8, 512, 1, 1024, 1, 1, 1, 0, ACT_RELU);
    run_conv(fc1, fc2w, fc2b, fc2, 1, 512, 1, 10, 512, 1, 1024, 1, 1, 1, 0, ACT_RELU);
    run_conv(fc2, hclsw, hclsb, out + OFF_ROICLS, 1, 512, 1, 10, 512, 1, 8, 1, 1, 1, 0, ACT_NONE);
    softmax8_kernel<<<2, 256>>>(out + OFF_ROICLS);
    run_conv(fc2, hregw, hregb, out + OFF_ROIREG, 1, 512, 1, 10, 512, 1, 32, 1, 1, 1, 0, ACT_NONE);

    // ---- anchors ----
    anchors_kernel<<<(159882 + 255) / 256, 256>>>(out + OFF_ANCH);
}

// round 10
// speedup vs baseline: 1.8266x; 1.8266x over previous
#include <cuda_runtime.h>
#include <cuda_bf16.h>
#include <mma.h>
#include <math.h>

using namespace nvcuda;

#define ACT_NONE 0
#define ACT_RELU 1
#define ACT_SIG  2

#define BM 128
#define BN 128
#define BKC 8

#define A_STR 40
#define B_STR 136

#define SC_M2     0L
#define SC_M3     (SC_M2 + 20480000L)
#define SC_M4     (SC_M3 + 5120000L)
#define SC_M5     (SC_M4 + 1280000L)
#define SC_P2     (SC_M5 + 320000L)
#define SC_P3     (SC_P2 + 20480000L)
#define SC_P4     (SC_P3 + 5120000L)
#define SC_P5     (SC_P4 + 1280000L)
#define SC_P6     (SC_P5 + 320000L)
#define SC_R      (SC_P6 + 86528L)
#define SC_POOL   (SC_R + 40960000L)
#define SC_FC1    (SC_POOL + 131072L)
#define SC_FC2    (SC_FC1 + 524288L)
#define SC_TOTAL  (SC_FC2 + 524288L)

__device__ __align__(16) float g_scratch[SC_TOTAL];

#define OFF_CLS2 0L
#define OFF_CLS3 240000L
#define OFF_CLS4 300000L
#define OFF_CLS5 315000L
#define OFF_CLS6 318750L
#define OFF_REG2 319764L
#define OFF_REG3 1279764L
#define OFF_REG4 1519764L
#define OFF_REG5 1579764L
#define OFF_REG6 1594764L
#define OFF_ROICLS 1598820L
#define OFF_ROIREG 1602916L
#define OFF_ANCH   1619300L

struct ConvParams {
    const float* in;
    const float* w;
    const float* bias;
    float* out;
    int Hin, Win, logCin;
    int Hout, Wout, Cout;
    int M;
    int KW, stride, pad, Ktot, act;
};

__device__ __forceinline__ void split_store(__nv_bfloat16* hi, __nv_bfloat16* lo, float4 v) {
    __nv_bfloat16 h0 = __float2bfloat16_rn(v.x);
    __nv_bfloat16 h1 = __float2bfloat16_rn(v.y);
    __nv_bfloat16 h2 = __float2bfloat16_rn(v.z);
    __nv_bfloat16 h3 = __float2bfloat16_rn(v.w);
    __nv_bfloat16 l0 = __float2bfloat16_rn(v.x - __bfloat162float(h0));
    __nv_bfloat16 l1 = __float2bfloat16_rn(v.y - __bfloat162float(h1));
    __nv_bfloat16 l2 = __float2bfloat16_rn(v.z - __bfloat162float(h2));
    __nv_bfloat16 l3 = __float2bfloat16_rn(v.w - __bfloat162float(h3));
    reinterpret_cast<__nv_bfloat162*>(hi)[0] = __nv_bfloat162(h0, h1);
    reinterpret_cast<__nv_bfloat162*>(hi)[1] = __nv_bfloat162(h2, h3);
    reinterpret_cast<__nv_bfloat162*>(lo)[0] = __nv_bfloat162(l0, l1);
    reinterpret_cast<__nv_bfloat162*>(lo)[1] = __nv_bfloat162(l2, l3);
}

__global__ __launch_bounds__(256) void conv_wmma(ConvParams p) {
    __shared__ __align__(16) __nv_bfloat16 AsH[128 * A_STR];
    __shared__ __align__(16) __nv_bfloat16 AsL[128 * A_STR];
    __shared__ __align__(16) __nv_bfloat16 BsH[32 * B_STR];
    __shared__ __align__(16) __nv_bfloat16 BsL[32 * B_STR];
    __shared__ __align__(16) float Cs[8 * 256];

    const int tid = threadIdx.x;
    const int lane = tid & 31;
    const int warp = tid >> 5;
    const int wm = warp >> 2;
    const int wn = warp & 3;
    const int m0 = blockIdx.x * 128;
    const int n0 = blockIdx.y * 128;

    const int arow = tid >> 1;
    const int ak0 = (tid & 1) << 4;
    const int am = m0 + arow;
    const bool am_ok = am < p.M;
    int aoh = 0;
    int aow = 0;
    const float* abase = p.in;
    if (am_ok) {
        int hw = p.Hout * p.Wout;
        int an = am / hw;
        int r = am - an * hw;
        aoh = r / p.Wout;
        aow = r - aoh * p.Wout;
        abase = p.in + (((long)an * p.Hin * p.Win) << p.logCin);
    }
    const int brow = tid >> 3;
    const int bcol0 = (tid & 7) << 4;
    const int cmask = (1 << p.logCin) - 1;

    wmma::fragment<wmma::accumulator, 16, 16, 16, float> acc[4][2];
#pragma unroll
    for (int mt = 0; mt < 4; mt++) {
#pragma unroll
        for (int nt = 0; nt < 2; nt++) {
            wmma::fill_fragment(acc[mt][nt], 0.0f);
        }
    }

    float4 aR[4];
    float4 bR[4];

    {
        bool ok = am_ok && (unsigned)(aoh * p.stride - p.pad) < (unsigned)p.Hin &&
                  (unsigned)(aow * p.stride - p.pad) < (unsigned)p.Win;
        int ih = aoh * p.stride - p.pad;
        int iw = aow * p.stride - p.pad;
        const float* src = abase + (((long)ih * p.Win + iw) << p.logCin) + ak0;
#pragma unroll
        for (int q = 0; q < 4; q++) {
            aR[q] = ok ? *reinterpret_cast<const float4*>(src + q * 4)
                       : make_float4(0.f, 0.f, 0.f, 0.f);
        }
        const float* wsrc = p.w + (long)brow * p.Cout + n0 + bcol0;
#pragma unroll
        for (int q = 0; q < 4; q++) {
            bR[q] = *reinterpret_cast<const float4*>(wsrc + q * 4);
        }
    }

    for (int kb = 0; kb < p.Ktot; kb += 32) {
#pragma unroll
        for (int q = 0; q < 4; q++) {
            int k = ak0 + q * 4;
            split_store(&AsH[arow * A_STR + k], &AsL[arow * A_STR + k], aR[q]);
        }
#pragma unroll
        for (int q = 0; q < 4; q++) {
            int c = bcol0 + q * 4;
            split_store(&BsH[brow * B_STR + c], &BsL[brow * B_STR + c], bR[q]);
        }
        __syncthreads();

        if (kb + 32 < p.Ktot) {
            int kn = kb + 32;
            int tap = kn >> p.logCin;
            int cib = kn & cmask;
            int dy = tap / p.KW;
            int dx = tap - dy * p.KW;
            int ih = aoh * p.stride + dy - p.pad;
            int iw = aow * p.stride + dx - p.pad;
            bool ok = am_ok && (unsigned)ih < (unsigned)p.Hin && (unsigned)iw < (unsigned)p.Win;
            const float* src = abase + (((long)ih * p.Win + iw) << p.logCin) + cib + ak0;
#pragma unroll
            for (int q = 0; q < 4; q++) {
                aR[q] = ok ? *reinterpret_cast<const float4*>(src + q * 4)
                           : make_float4(0.f, 0.f, 0.f, 0.f);
            }
            const float* wsrc = p.w + (long)(kn + brow) * p.Cout + n0 + bcol0;
#pragma unroll
            for (int q = 0; q < 4; q++) {
                bR[q] = *reinterpret_cast<const float4*>(wsrc + q * 4);
            }
        }

#pragma unroll
        for (int ks = 0; ks < 2; ks++) {
            wmma::fragment<wmma::matrix_a, 16, 16, 16, __nv_bfloat16, wmma::row_major> fAH[4];
            wmma::fragment<wmma::matrix_a, 16, 16, 16, __nv_bfloat16, wmma::row_major> fAL[4];
            wmma::fragment<wmma::matrix_b, 16, 16, 16, __nv_bfloat16, wmma::row_major> fBH[2];
            wmma::fragment<wmma::matrix_b, 16, 16, 16, __nv_bfloat16, wmma::row_major> fBL[2];
#pragma unroll
            for (int mt = 0; mt < 4; mt++) {
                int row = wm * 64 + mt * 16;
                int col = ks * 16;
                wmma::load_matrix_sync(fAH[mt], &AsH[row * A_STR + col], A_STR);
                wmma::load_matrix_sync(fAL[mt], &AsL[row * A_STR + col], A_STR);
            }
#pragma unroll
            for (int nt = 0; nt < 2; nt++) {
                int krow = ks * 16;
                int bc = wn * 32 + nt * 16;
                wmma::load_matrix_sync(fBH[nt], &BsH[krow * B_STR + bc], B_STR);
                wmma::load_matrix_sync(fBL[nt], &BsL[krow * B_STR + bc], B_STR);
            }
#pragma unroll
            for (int mt = 0; mt < 4; mt++) {
#pragma unroll
                for (int nt = 0; nt < 2; nt++) {
                    wmma::mma_sync(acc[mt][nt], fAH[mt], fBH[nt], acc[mt][nt]);
                    wmma::mma_sync(acc[mt][nt], fAH[mt], fBL[nt], acc[mt][nt]);
                    wmma::mma_sync(acc[mt][nt], fAL[mt], fBH[nt], acc[mt][nt]);
                }
            }
        }
        __syncthreads();
    }

    float* cwarp = Cs + warp * 256;
#pragma unroll
    for (int mt = 0; mt < 4; mt++) {
#pragma unroll
        for (int nt = 0; nt < 2; nt++) {
            wmma::store_matrix_sync(cwarp, acc[mt][nt], 16, wmma::mem_row_major);
            __syncwarp();
#pragma unroll
            for (int e = 0; e < 8; e++) {
                int idx = e * 32 + lane;
                int r = idx >> 4;
                int cc = idx & 15;
                int m = m0 + wm * 64 + mt * 16 + r;
                int n = n0 + wn * 32 + nt * 16 + cc;
                if (m < p.M) {
                    float v = cwarp[idx] + p.bias[n];
                    if (p.act == ACT_RELU) v = fmaxf(v, 0.f);
                    p.out[(long)m * p.Cout + n] = v;
                }
            }
            __syncwarp();
        }
    }
}

__global__ __launch_bounds__(256) void conv_gemm(ConvParams p) {
    __shared__ float As[BKC][BM];
    __shared__ float Bs[BKC][BN];
    const int tid = threadIdx.x;
    const int m0 = blockIdx.x * BM;
    const int n0 = blockIdx.y * BN;

    const int arow = tid >> 1;
    const int kq = (tid & 1) << 2;
    const int am = m0 + arow;
    const bool am_ok = am < p.M;
    int aoh = 0;
    int aow = 0;
    const float* abase = p.in;
    if (am_ok) {
        int hw = p.Hout * p.Wout;
        int an = am / hw;
        int r = am - an * hw;
        aoh = r / p.Wout;
        aow = r - aoh * p.Wout;
        abase = p.in + (((long)an * p.Hin * p.Win) << p.logCin);
    }
    const int brow = tid >> 5;
    const int bcol = (tid & 31) << 2;
    const bool bvec = ((p.Cout & 3) == 0) && (n0 + BN <= p.Cout);
    const int cmask = (1 << p.logCin) - 1;

    float acc[8][8];
#pragma unroll
    for (int i = 0; i < 8; i++) {
#pragma unroll
        for (int j = 0; j < 8; j++) {
            acc[i][j] = 0.f;
        }
    }

    const int ty = tid >> 4;
    const int tx = tid & 15;

    for (int kb = 0; kb < p.Ktot; kb += BKC) {
        float4 av = make_float4(0.f, 0.f, 0.f, 0.f);
        if (am_ok) {
            int k0 = kb + kq;
            int tap = k0 >> p.logCin;
            int ci = k0 & cmask;
            int dy = tap / p.KW;
            int dx = tap - dy * p.KW;
            int ih = aoh * p.stride + dy - p.pad;
            int iw = aow * p.stride + dx - p.pad;
            if ((unsigned)ih < (unsigned)p.Hin && (unsigned)iw < (unsigned)p.Win) {
                av = *reinterpret_cast<const float4*>(
                    abase + (((long)ih * p.Win + iw) << p.logCin) + ci);
            }
        }
        As[kq + 0][arow] = av.x;
        As[kq + 1][arow] = av.y;
        As[kq + 2][arow] = av.z;
        As[kq + 3][arow] = av.w;
        {
            int kB = kb + brow;
            const float* wp = p.w + (long)kB * p.Cout + n0 + bcol;
            float4 bv;
            if (bvec) {
                bv = *reinterpret_cast<const float4*>(wp);
            } else {
                int nb = n0 + bcol;
                bv.x = (nb + 0 < p.Cout) ? wp[0] : 0.f;
                bv.y = (nb + 1 < p.Cout) ? wp[1] : 0.f;
                bv.z = (nb + 2 < p.Cout) ? wp[2] : 0.f;
                bv.w = (nb + 3 < p.Cout) ? wp[3] : 0.f;
            }
            *reinterpret_cast<float4*>(&Bs[brow][bcol]) = bv;
        }
        __syncthreads();
#pragma unroll
        for (int kk = 0; kk < BKC; kk++) {
            float4 a0 = *reinterpret_cast<const float4*>(&As[kk][ty << 3]);
            float4 a1 = *reinterpret_cast<const float4*>(&As[kk][(ty << 3) + 4]);
            float4 b0 = *reinterpret_cast<const float4*>(&Bs[kk][tx << 3]);
            float4 b1 = *reinterpret_cast<const float4*>(&Bs[kk][(tx << 3) + 4]);
            float ra[8] = {a0.x, a0.y, a0.z, a0.w, a1.x, a1.y, a1.z, a1.w};
            float rb[8] = {b0.x, b0.y, b0.z, b0.w, b1.x, b1.y, b1.z, b1.w};
#pragma unroll
            for (int i = 0; i < 8; i++) {
#pragma unroll
                for (int j = 0; j < 8; j++) {
                    acc[i][j] += ra[i] * rb[j];
                }
            }
        }
        __syncthreads();
    }

#pragma unroll
    for (int i = 0; i < 8; i++) {
        int m = m0 + (ty << 3) + i;
        if (m >= p.M) continue;
#pragma unroll
        for (int j = 0; j < 8; j++) {
            int n = n0 + (tx << 3) + j;
            if (n >= p.Cout) continue;
            float v = acc[i][j] + p.bias[n];
            if (p.act == ACT_RELU) v = fmaxf(v, 0.f);
            else if (p.act == ACT_SIG) v = 1.f / (1.f + expf(-v));
            p.out[(long)m * p.Cout + n] = v;
        }
    }
}

__global__ void up2_add_kernel(float* dst, const float* src, int H, int W, int total) {
    int i = blockIdx.x * blockDim.x + threadIdx.x;
    if (i >= total) return;
    int c = i & 255;
    int t = i >> 8;
    int w = t % W;
    t /= W;
    int h = t % H;
    int n = t / H;
    int Hs = H >> 1;
    int Ws = W >> 1;
    dst[i] += src[((((long)n * Hs + (h >> 1)) * Ws + (w >> 1)) << 8) + c];
}

__global__ void roi_pool_kernel(const float* fm, const float* rois, float* pooled) {
    int roi = blockIdx.x;
    int c = threadIdx.x;
    __shared__ int sy0[7], sy1[7], sx0[7], sx1[7];
    __shared__ float swy[7], swx[7];
    __shared__ int svy[7], svx[7];
    if (c == 0) {
        float y1 = rois[roi * 4 + 0] / 50.0f;
        float x1 = rois[roi * 4 + 1] / 50.0f;
        float y2 = rois[roi * 4 + 2] / 50.0f;
        float x2 = rois[roi * 4 + 3] / 50.0f;
        for (int i = 0; i < 7; i++) {
            float ys = y1 * 49.0f + (float)i * ((y2 - y1) * 49.0f / 6.0f);
            float xs = x1 * 49.0f + (float)i * ((x2 - x1) * 49.0f / 6.0f);
            float fy = floorf(ys);
            float fx = floorf(xs);
            int iy0 = min(max((int)fy, 0), 49);
            int ix0 = min(max((int)fx, 0), 49);
            sy0[i] = iy0;
            sy1[i] = min(iy0 + 1, 49);
            sx0[i] = ix0;
            sx1[i] = min(ix0 + 1, 49);
            swy[i] = ys - fy;
            swx[i] = xs - fx;
            svy[i] = (ys >= 0.0f && ys <= 49.0f) ? 1 : 0;
            svx[i] = (xs >= 0.0f && xs <= 49.0f) ? 1 : 0;
        }
    }
    __syncthreads();
    float acc = 0.f;
    for (int iy = 0; iy < 7; iy++) {
        if (!svy[iy]) continue;
        float wy = swy[iy];
        const float* r0 = fm + ((long)sy0[iy] * 50 << 8);
        const float* r1 = fm + ((long)sy1[iy] * 50 << 8);
        for (int ix = 0; ix < 7; ix++) {
            if (!svx[ix]) continue;
            float wx = swx[ix];
            float v00 = r0[(sx0[ix] << 8) + c];
            float v01 = r0[(sx1[ix] << 8) + c];
            float v10 = r1[(sx0[ix] << 8) + c];
            float v11 = r1[(sx1[ix] << 8) + c];
            acc += (1.f - wy) * (1.f - wx) * v00 + (1.f - wy) * wx * v01 +
                   wy * (1.f - wx) * v10 + wy * wx * v11;
        }
    }
    pooled[(roi << 8) + c] = acc * (1.0f / 49.0f);
}

__global__ void softmax8_kernel(float* x) {
    int r = blockIdx.x * blockDim.x + threadIdx.x;
    if (r >= 512) return;
    float* p = x + r * 8;
    float m = p[0];
#pragma unroll
    for (int i = 1; i < 8; i++) {
        m = fmaxf(m, p[i]);
    }
    float e[8];
    float s = 0.f;
#pragma unroll
    for (int i = 0; i < 8; i++) {
        e[i] = expf(p[i] - m);
        s += e[i];
    }
    float inv = 1.0f / s;
#pragma unroll
    for (int i = 0; i < 8; i++) {
        p[i] = e[i] * inv;
    }
}

__global__ void anchors_kernel(float* out) {
    int idx = blockIdx.x * blockDim.x + threadIdx.x;
    if (idx >= 159882) return;
    int lvl;
    int a;
    if (idx < 120000)      { lvl = 0; a = idx; }
    else if (idx < 150000) { lvl = 1; a = idx - 120000; }
    else if (idx < 157500) { lvl = 2; a = idx - 150000; }
    else if (idx < 159375) { lvl = 3; a = idx - 157500; }
    else                   { lvl = 4; a = idx - 159375; }
    const int   ws[5]  = {200, 100, 50, 25, 13};
    const float scl[5] = {32.f, 64.f, 128.f, 256.f, 512.f};
    const float st[5]  = {4.f, 8.f, 16.f, 32.f, 64.f};
    const float sq[3]  = {0.70710678118654752f, 1.0f, 1.41421356237309505f};
    int r = a % 3;
    int cell = a / 3;
    int w = ws[lvl];
    int y = cell / w;
    int x = cell - y * w;
    float sx = (float)x * st[lvl];
    float sy = (float)y * st[lvl];
    float s = scl[lvl];
    float hx = s * sq[r] * 0.5f;
    float hy = s / sq[r] * 0.5f;
    out[idx * 4 + 0] = sx - hx;
    out[idx * 4 + 1] = sy - hy;
    out[idx * 4 + 2] = sx + hx;
    out[idx * 4 + 3] = sy + hy;
}

static void run_conv(const float* in, const float* w, const float* b, float* out,
                     int Nb, int Hin, int Win, int logCin,
                     int Hout, int Wout, int Cout,
                     int KW, int KH, int stride, int pad, int act) {
    ConvParams p;
    p.in = in;
    p.w = w;
    p.bias = b;
    p.out = out;
    p.Hin = Hin;
    p.Win = Win;
    p.logCin = logCin;
    p.Hout = Hout;
    p.Wout = Wout;
    p.Cout = Cout;
    p.M = Nb * Hout * Wout;
    p.KW = KW;
    p.stride = stride;
    p.pad = pad;
    p.Ktot = (KH * KW) << logCin;
    p.act = act;
    if ((Cout % 128) == 0 && (p.Ktot % 32) == 0 && act != ACT_SIG) {
        dim3 grid((p.M + 127) / 128, Cout / 128);
        conv_wmma<<<grid, 256>>>(p);
    } else {
        dim3 grid((p.M + BM - 1) / BM, (Cout + BN - 1) / BN);
        conv_gemm<<<grid, 256>>>(p);
    }
}

extern "C" void kernel_launch(void* const* d_in, const int* in_sizes, int n_in,
                              void* d_out, int out_size) {
    const float* feat2 = (const float*)d_in[0];
    const float* feat3 = (const float*)d_in[1];
    const float* feat4 = (const float*)d_in[2];
    const float* feat5 = (const float*)d_in[3];
    const float* rois  = (const float*)d_in[4];
    const float* lw2 = (const float*)d_in[5];
    const float* lb2 = (const float*)d_in[6];
    const float* lw3 = (const float*)d_in[7];
    const float* lb3 = (const float*)d_in[8];
    const float* lw4 = (const float*)d_in[9];
    const float* lb4 = (const float*)d_in[10];
    const float* lw5 = (const float*)d_in[11];
    const float* lb5 = (const float*)d_in[12];
    const float* fw  = (const float*)d_in[13];
    const float* fb  = (const float*)d_in[14];
    const float* p6w = (const float*)d_in[15];
    const float* p6b = (const float*)d_in[16];
    const float* rpnw = (const float*)d_in[17];
    const float* rpnb = (const float*)d_in[18];
    const float* clsw = (const float*)d_in[19];
    const float* clsb = (const float*)d_in[20];
    const float* regw = (const float*)d_in[21];
    const float* regb = (const float*)d_in[22];
    const float* fc1w = (const float*)d_in[23];
    const float* fc1b = (const float*)d_in[24];
    const float* fc2w = (const float*)d_in[25];
    const float* fc2b = (const float*)d_in[26];
    const float* hclsw = (const float*)d_in[27];
    const float* hclsb = (const float*)d_in[28];
    const float* hregw = (const float*)d_in[29];
    const float* hregb = (const float*)d_in[30];
    float* out = (float*)d_out;

    float* sc = 0;
    cudaGetSymbolAddress((void**)&sc, g_scratch);
    float* m2 = sc + SC_M2;
    float* m3 = sc + SC_M3;
    float* m4 = sc + SC_M4;
    float* m5 = sc + SC_M5;
    float* p2 = sc + SC_P2;
    float* p3 = sc + SC_P3;
    float* p4 = sc + SC_P4;
    float* p5 = sc + SC_P5;
    float* p6 = sc + SC_P6;
    float* rbuf = sc + SC_R;
    float* pooled = sc + SC_POOL;
    float* fc1 = sc + SC_FC1;
    float* fc2 = sc + SC_FC2;

    run_conv(feat5, lw5, lb5, m5, 2, 25, 25, 11, 25, 25, 256, 1, 1, 1, 0, ACT_NONE);
    run_conv(feat4, lw4, lb4, m4, 2, 50, 50, 10, 50, 50, 256, 1, 1, 1, 0, ACT_NONE);
    {
        int tot = 2 * 50 * 50 * 256;
        up2_add_kernel<<<(tot + 255) / 256, 256>>>(m4, m5, 50, 50, tot);
    }
    run_conv(feat3, lw3, lb3, m3, 2, 100, 100, 9, 100, 100, 256, 1, 1, 1, 0, ACT_NONE);
    {
        int tot = 2 * 100 * 100 * 256;
        up2_add_kernel<<<(tot + 255) / 256, 256>>>(m3, m4, 100, 100, tot);
    }
    run_conv(feat2, lw2, lb2, m2, 2, 200, 200, 8, 200, 200, 256, 1, 1, 1, 0, ACT_NONE);
    {
        int tot = 2 * 200 * 200 * 256;
        up2_add_kernel<<<(tot + 255) / 256, 256>>>(m2, m3, 200, 200, tot);
    }

    run_conv(m2, fw + 0L * 589824L, fb + 0,   p2, 2, 200, 200, 8, 200, 200, 256, 3, 3, 1, 1, ACT_NONE);
    run_conv(m3, fw + 1L * 589824L, fb + 256, p3, 2, 100, 100, 8, 100, 100, 256, 3, 3, 1, 1, ACT_NONE);
    run_conv(m4, fw + 2L * 589824L, fb + 512, p4, 2, 50, 50, 8, 50, 50, 256, 3, 3, 1, 1, ACT_NONE);
    run_conv(m5, fw + 3L * 589824L, fb + 768, p5, 2, 25, 25, 8, 25, 25, 256, 3, 3, 1, 1, ACT_NONE);
    run_conv(p5, p6w, p6b, p6, 2, 25, 25, 8, 13, 13, 256, 3, 3, 2, 1, ACT_NONE);

    struct Lv { const float* f; int H; int W; long co; long ro; };
    Lv lv[5] = {
        {p2, 200, 200, OFF_CLS2, OFF_REG2},
        {p3, 100, 100, OFF_CLS3, OFF_REG3},
        {p4,  50,  50, OFF_CLS4, OFF_REG4},
        {p5,  25,  25, OFF_CLS5, OFF_REG5},
        {p6,  13,  13, OFF_CLS6, OFF_REG6}
    };
    for (int i = 0; i < 5; i++) {
        run_conv(lv[i].f, rpnw, rpnb, rbuf, 2, lv[i].H, lv[i].W, 8,
                 lv[i].H, lv[i].W, 512, 3, 3, 1, 1, ACT_RELU);
        run_conv(rbuf, clsw, clsb, out + lv[i].co, 2, lv[i].H, lv[i].W, 9,
                 lv[i].H, lv[i].W, 3, 1, 1, 1, 0, ACT_SIG);
        run_conv(rbuf, regw, regb, out + lv[i].ro, 2, lv[i].H, lv[i].W, 9,
                 lv[i].H, lv[i].W, 12, 1, 1, 1, 0, ACT_NONE);
    }

    roi_pool_kernel<<<512, 256>>>(p4, rois, pooled);
    run_conv(pooled, fc1w, fc1b, fc1, 1, 512, 1, 8, 512, 1, 1024, 1, 1, 1, 0, ACT_RELU);
    run_conv(fc1, fc2w, fc2b, fc2, 1, 512, 1, 10, 512, 1, 1024, 1, 1, 1, 0, ACT_RELU);
    run_conv(fc2, hclsw, hclsb, out + OFF_ROICLS, 1, 512, 1, 10, 512, 1, 8, 1, 1, 1, 0, ACT_NONE);
    softmax8_kernel<<<2, 256>>>(out + OFF_ROICLS);
    run_conv(fc2, hregw, hregb, out + OFF_ROIREG, 1, 512, 1, 10, 512, 1, 32, 1, 1, 1, 0, ACT_NONE);

    anchors_kernel<<<(159882 + 255) / 256, 256>>>(out + OFF_ANCH);
}

// round 11
// speedup vs baseline: 2.3657x; 1.2952x over previous
#include <cuda_runtime.h>
#include <cuda_bf16.h>
#include <cuda_pipeline.h>
#include <mma.h>
#include <math.h>

using namespace nvcuda;

#define ACT_NONE 0
#define ACT_RELU 1
#define ACT_SIG  2

#define BM 128
#define BN 128
#define BKC 8

#define A_STR 24
#define B_STR 136
#define SMEM_DYN 41984

// ---------------- fp32 scratch ----------------
#define SC_M2     0L
#define SC_M3     (SC_M2 + 20480000L)
#define SC_M4     (SC_M3 + 5120000L)
#define SC_M5     (SC_M4 + 1280000L)
#define SC_P2     (SC_M5 + 320000L)
#define SC_P3     (SC_P2 + 20480000L)
#define SC_P4     (SC_P3 + 5120000L)
#define SC_P5     (SC_P4 + 1280000L)
#define SC_P6     (SC_P5 + 320000L)
#define SC_R      (SC_P6 + 86528L)
#define SC_POOL   (SC_R + 40960000L)
#define SC_FC1    (SC_POOL + 131072L)
#define SC_FC2    (SC_FC1 + 524288L)
#define SC_TOTAL  (SC_FC2 + 524288L)

__device__ __align__(16) float g_scratch[SC_TOTAL];

// ---------------- bf16 hi/lo scratch ----------------
#define B_F2H 0L
#define B_F2L (B_F2H + 20480000L)
#define B_F3H (B_F2L + 20480000L)
#define B_F3L (B_F3H + 10240000L)
#define B_F4H (B_F3L + 10240000L)
#define B_F4L (B_F4H + 5120000L)
#define B_F5H (B_F4L + 5120000L)
#define B_F5L (B_F5H + 2560000L)
#define B_M2H (B_F5L + 2560000L)
#define B_M2L (B_M2H + 20480000L)
#define B_M3H (B_M2L + 20480000L)
#define B_M3L (B_M3H + 5120000L)
#define B_M4H (B_M3L + 5120000L)
#define B_M4L (B_M4H + 1280000L)
#define B_M5H (B_M4L + 1280000L)
#define B_M5L (B_M5H + 320000L)
#define B_P2H (B_M5L + 320000L)
#define B_P2L (B_P2H + 20480000L)
#define B_P3H (B_P2L + 20480000L)
#define B_P3L (B_P3H + 5120000L)
#define B_P4H (B_P3L + 5120000L)
#define B_P4L (B_P4H + 1280000L)
#define B_P5H (B_P4L + 1280000L)
#define B_P5L (B_P5H + 320000L)
#define B_P6H (B_P5L + 320000L)
#define B_P6L (B_P6H + 86528L)
#define B_POOLH (B_P6L + 86528L)
#define B_POOLL (B_POOLH + 131072L)
#define B_FC1H (B_POOLL + 131072L)
#define B_FC1L (B_FC1H + 524288L)
#define B_FC2H (B_FC1L + 524288L)
#define B_FC2L (B_FC2H + 524288L)
#define B_WL2H (B_FC2L + 524288L)
#define B_WL2L (B_WL2H + 65536L)
#define B_WL3H (B_WL2L + 65536L)
#define B_WL3L (B_WL3H + 131072L)
#define B_WL4H (B_WL3L + 131072L)
#define B_WL4L (B_WL4H + 262144L)
#define B_WL5H (B_WL4L + 262144L)
#define B_WL5L (B_WL5H + 524288L)
#define B_WFWH (B_WL5L + 524288L)
#define B_WFWL (B_WFWH + 2359296L)
#define B_WP6H (B_WFWL + 2359296L)
#define B_WP6L (B_WP6H + 589824L)
#define B_WRPNH (B_WP6L + 589824L)
#define B_WRPNL (B_WRPNH + 1179648L)
#define B_WFC1H (B_WRPNL + 1179648L)
#define B_WFC1L (B_WFC1H + 262144L)
#define B_WFC2H (B_WFC1L + 262144L)
#define B_WFC2L (B_WFC2H + 1048576L)
#define B_TOTAL (B_WFC2L + 1048576L)

__device__ __align__(16) __nv_bfloat16 g_bscratch[B_TOTAL];

// ---------------- output offsets ----------------
#define OFF_CLS2 0L
#define OFF_CLS3 240000L
#define OFF_CLS4 300000L
#define OFF_CLS5 315000L
#define OFF_CLS6 318750L
#define OFF_REG2 319764L
#define OFF_REG3 1279764L
#define OFF_REG4 1519764L
#define OFF_REG5 1579764L
#define OFF_REG6 1594764L
#define OFF_ROICLS 1598820L
#define OFF_ROIREG 1602916L
#define OFF_ANCH   1619300L

struct ConvParams {
    const float* in;
    const float* w;
    const float* bias;
    float* out;
    int Hin, Win, logCin;
    int Hout, Wout, Cout;
    int M;
    int KW, stride, pad, Ktot, act;
};

struct Conv2Params {
    const __nv_bfloat16* aHi;
    const __nv_bfloat16* aLo;
    const __nv_bfloat16* wHi;
    const __nv_bfloat16* wLo;
    const float* bias;
    float* out;
    int Hin, Win, logCin;
    int Hout, Wout, Cout;
    int M;
    int KW, stride, pad, Ktot, act;
};

__device__ __forceinline__ void split_store(__nv_bfloat16* hi, __nv_bfloat16* lo, float4 v) {
    __nv_bfloat16 h0 = __float2bfloat16_rn(v.x);
    __nv_bfloat16 h1 = __float2bfloat16_rn(v.y);
    __nv_bfloat16 h2 = __float2bfloat16_rn(v.z);
    __nv_bfloat16 h3 = __float2bfloat16_rn(v.w);
    __nv_bfloat16 l0 = __float2bfloat16_rn(v.x - __bfloat162float(h0));
    __nv_bfloat16 l1 = __float2bfloat16_rn(v.y - __bfloat162float(h1));
    __nv_bfloat16 l2 = __float2bfloat16_rn(v.z - __bfloat162float(h2));
    __nv_bfloat16 l3 = __float2bfloat16_rn(v.w - __bfloat162float(h3));
    reinterpret_cast<__nv_bfloat162*>(hi)[0] = __nv_bfloat162(h0, h1);
    reinterpret_cast<__nv_bfloat162*>(hi)[1] = __nv_bfloat162(h2, h3);
    reinterpret_cast<__nv_bfloat162*>(lo)[0] = __nv_bfloat162(l0, l1);
    reinterpret_cast<__nv_bfloat162*>(lo)[1] = __nv_bfloat162(l2, l3);
}

// fp32 -> (hi, lo) bf16 conversion pass
__global__ void cvt_split(const float* src, __nv_bfloat16* hi, __nv_bfloat16* lo, int n4) {
    int i = blockIdx.x * blockDim.x + threadIdx.x;
    if (i >= n4) return;
    float4 v = reinterpret_cast<const float4*>(src)[i];
    split_store(hi + (long)i * 4, lo + (long)i * 4, v);
}

// issue one 16-k stage of cp.async loads (4 x 16B per thread)
__device__ __forceinline__ void issue_stage(
    const Conv2Params& p, int kb, int st,
    __nv_bfloat16* AsH, __nv_bfloat16* AsL,
    __nv_bfloat16* BsH, __nv_bfloat16* BsL,
    long aBase, bool am_ok, int aoh, int aow,
    int arow, int kseg, int krow, int cseg, int n0)
{
    int k0 = kb + kseg;
    int tap = k0 >> p.logCin;
    int ci = k0 & ((1 << p.logCin) - 1);
    int dy = tap / p.KW;
    int dx = tap - dy * p.KW;
    int ih = aoh * p.stride + dy - p.pad;
    int iw = aow * p.stride + dx - p.pad;
    bool ok = am_ok && (unsigned)ih < (unsigned)p.Hin && (unsigned)iw < (unsigned)p.Win;
    size_t zf = ok ? 0 : 16;
    long src = ok ? (aBase + (((long)ih * p.Win + iw) << p.logCin) + ci) : 0;
    __pipeline_memcpy_async(AsH + st * 3072 + arow * A_STR + kseg, p.aHi + src, 16, zf);
    __pipeline_memcpy_async(AsL + st * 3072 + arow * A_STR + kseg, p.aLo + src, 16, zf);
    long wsrc = (long)(kb + krow) * p.Cout + n0 + cseg;
    __pipeline_memcpy_async(BsH + st * 2176 + krow * B_STR + cseg, p.wHi + wsrc, 16, (size_t)0);
    __pipeline_memcpy_async(BsL + st * 2176 + krow * B_STR + cseg, p.wLo + wsrc, 16, (size_t)0);
}

__global__ __launch_bounds__(256, 2) void conv_wmma2(Conv2Params p) {
    extern __shared__ __nv_bfloat16 smem[];
    __nv_bfloat16* AsH = smem;
    __nv_bfloat16* AsL = smem + 6144;
    __nv_bfloat16* BsH = smem + 12288;
    __nv_bfloat16* BsL = smem + 16640;

    const int tid = threadIdx.x;
    const int lane = tid & 31;
    const int warp = tid >> 5;
    const int wm = warp >> 2;
    const int wn = warp & 3;
    const int m0 = blockIdx.x * 128;
    const int n0 = blockIdx.y * 128;

    // loader mapping: one 16B chunk per thread per array
    const int arow = tid >> 1;
    const int kseg = (tid & 1) << 3;
    const int krow = tid >> 4;
    const int cseg = (tid & 15) << 3;

    const int am = m0 + arow;
    const bool am_ok = am < p.M;
    int aoh = 0;
    int aow = 0;
    long aBase = 0;
    if (am_ok) {
        int hw = p.Hout * p.Wout;
        int an = am / hw;
        int r = am - an * hw;
        aoh = r / p.Wout;
        aow = r - aoh * p.Wout;
        aBase = ((long)an * p.Hin * p.Win) << p.logCin;
    }

    wmma::fragment<wmma::accumulator, 16, 16, 16, float> acc[4][2];
#pragma unroll
    for (int mt = 0; mt < 4; mt++) {
#pragma unroll
        for (int nt = 0; nt < 2; nt++) {
            wmma::fill_fragment(acc[mt][nt], 0.0f);
        }
    }

    const int nK = p.Ktot >> 4;

    issue_stage(p, 0, 0, AsH, AsL, BsH, BsL, aBase, am_ok, aoh, aow, arow, kseg, krow, cseg, n0);
    __pipeline_commit();

    for (int kt = 0; kt < nK; kt++) {
        if (kt + 1 < nK) {
            issue_stage(p, (kt + 1) << 4, (kt + 1) & 1, AsH, AsL, BsH, BsL,
                        aBase, am_ok, aoh, aow, arow, kseg, krow, cseg, n0);
        }
        __pipeline_commit();
        __pipeline_wait_prior(1);
        __syncthreads();

        const int st = kt & 1;
        const __nv_bfloat16* aH = AsH + st * 3072;
        const __nv_bfloat16* aL = AsL + st * 3072;
        const __nv_bfloat16* bH = BsH + st * 2176;
        const __nv_bfloat16* bL = BsL + st * 2176;

        wmma::fragment<wmma::matrix_b, 16, 16, 16, __nv_bfloat16, wmma::row_major> fBH[2];
        wmma::fragment<wmma::matrix_b, 16, 16, 16, __nv_bfloat16, wmma::row_major> fBL[2];
#pragma unroll
        for (int nt = 0; nt < 2; nt++) {
            int bc = wn * 32 + nt * 16;
            wmma::load_matrix_sync(fBH[nt], bH + bc, B_STR);
            wmma::load_matrix_sync(fBL[nt], bL + bc, B_STR);
        }
#pragma unroll
        for (int mt = 0; mt < 4; mt++) {
            wmma::fragment<wmma::matrix_a, 16, 16, 16, __nv_bfloat16, wmma::row_major> fAH;
            wmma::fragment<wmma::matrix_a, 16, 16, 16, __nv_bfloat16, wmma::row_major> fAL;
            int row = wm * 64 + mt * 16;
            wmma::load_matrix_sync(fAH, aH + row * A_STR, A_STR);
            wmma::load_matrix_sync(fAL, aL + row * A_STR, A_STR);
#pragma unroll
            for (int nt = 0; nt < 2; nt++) {
                wmma::mma_sync(acc[mt][nt], fAH, fBH[nt], acc[mt][nt]);
                wmma::mma_sync(acc[mt][nt], fAH, fBL[nt], acc[mt][nt]);
                wmma::mma_sync(acc[mt][nt], fAL, fBH[nt], acc[mt][nt]);
            }
        }
        __syncthreads();
    }

    // epilogue: stage accumulators through smem (reuse stage buffers)
    float* Cs = reinterpret_cast<float*>(smem);
    float* cwarp = Cs + warp * 256;
#pragma unroll
    for (int mt = 0; mt < 4; mt++) {
#pragma unroll
        for (int nt = 0; nt < 2; nt++) {
            wmma::store_matrix_sync(cwarp, acc[mt][nt], 16, wmma::mem_row_major);
            __syncwarp();
#pragma unroll
            for (int e = 0; e < 8; e++) {
                int idx = e * 32 + lane;
                int r = idx >> 4;
                int cc = idx & 15;
                int m = m0 + wm * 64 + mt * 16 + r;
                int n = n0 + wn * 32 + nt * 16 + cc;
                if (m < p.M) {
                    float v = cwarp[idx] + p.bias[n];
                    if (p.act == ACT_RELU) v = fmaxf(v, 0.f);
                    p.out[(long)m * p.Cout + n] = v;
                }
            }
            __syncwarp();
        }
    }
}

// ======================= fp32 fallback GEMM (small heads) =======================
__global__ __launch_bounds__(256) void conv_gemm(ConvParams p) {
    __shared__ float As[BKC][BM];
    __shared__ float Bs[BKC][BN];
    const int tid = threadIdx.x;
    const int m0 = blockIdx.x * BM;
    const int n0 = blockIdx.y * BN;

    const int arow = tid >> 1;
    const int kq = (tid & 1) << 2;
    const int am = m0 + arow;
    const bool am_ok = am < p.M;
    int aoh = 0;
    int aow = 0;
    const float* abase = p.in;
    if (am_ok) {
        int hw = p.Hout * p.Wout;
        int an = am / hw;
        int r = am - an * hw;
        aoh = r / p.Wout;
        aow = r - aoh * p.Wout;
        abase = p.in + (((long)an * p.Hin * p.Win) << p.logCin);
    }
    const int brow = tid >> 5;
    const int bcol = (tid & 31) << 2;
    const bool bvec = ((p.Cout & 3) == 0) && (n0 + BN <= p.Cout);
    const int cmask = (1 << p.logCin) - 1;

    float acc[8][8];
#pragma unroll
    for (int i = 0; i < 8; i++) {
#pragma unroll
        for (int j = 0; j < 8; j++) {
            acc[i][j] = 0.f;
        }
    }

    const int ty = tid >> 4;
    const int tx = tid & 15;

    for (int kb = 0; kb < p.Ktot; kb += BKC) {
        float4 av = make_float4(0.f, 0.f, 0.f, 0.f);
        if (am_ok) {
            int k0 = kb + kq;
            int tap = k0 >> p.logCin;
            int ci = k0 & cmask;
            int dy = tap / p.KW;
            int dx = tap - dy * p.KW;
            int ih = aoh * p.stride + dy - p.pad;
            int iw = aow * p.stride + dx - p.pad;
            if ((unsigned)ih < (unsigned)p.Hin && (unsigned)iw < (unsigned)p.Win) {
                av = *reinterpret_cast<const float4*>(
                    abase + (((long)ih * p.Win + iw) << p.logCin) + ci);
            }
        }
        As[kq + 0][arow] = av.x;
        As[kq + 1][arow] = av.y;
        As[kq + 2][arow] = av.z;
        As[kq + 3][arow] = av.w;
        {
            int kB = kb + brow;
            const float* wp = p.w + (long)kB * p.Cout + n0 + bcol;
            float4 bv;
            if (bvec) {
                bv = *reinterpret_cast<const float4*>(wp);
            } else {
                int nb = n0 + bcol;
                bv.x = (nb + 0 < p.Cout) ? wp[0] : 0.f;
                bv.y = (nb + 1 < p.Cout) ? wp[1] : 0.f;
                bv.z = (nb + 2 < p.Cout) ? wp[2] : 0.f;
                bv.w = (nb + 3 < p.Cout) ? wp[3] : 0.f;
            }
            *reinterpret_cast<float4*>(&Bs[brow][bcol]) = bv;
        }
        __syncthreads();
#pragma unroll
        for (int kk = 0; kk < BKC; kk++) {
            float4 a0 = *reinterpret_cast<const float4*>(&As[kk][ty << 3]);
            float4 a1 = *reinterpret_cast<const float4*>(&As[kk][(ty << 3) + 4]);
            float4 b0 = *reinterpret_cast<const float4*>(&Bs[kk][tx << 3]);
            float4 b1 = *reinterpret_cast<const float4*>(&Bs[kk][(tx << 3) + 4]);
            float ra[8] = {a0.x, a0.y, a0.z, a0.w, a1.x, a1.y, a1.z, a1.w};
            float rb[8] = {b0.x, b0.y, b0.z, b0.w, b1.x, b1.y, b1.z, b1.w};
#pragma unroll
            for (int i = 0; i < 8; i++) {
#pragma unroll
                for (int j = 0; j < 8; j++) {
                    acc[i][j] += ra[i] * rb[j];
                }
            }
        }
        __syncthreads();
    }

#pragma unroll
    for (int i = 0; i < 8; i++) {
        int m = m0 + (ty << 3) + i;
        if (m >= p.M) continue;
#pragma unroll
        for (int j = 0; j < 8; j++) {
            int n = n0 + (tx << 3) + j;
            if (n >= p.Cout) continue;
            float v = acc[i][j] + p.bias[n];
            if (p.act == ACT_RELU) v = fmaxf(v, 0.f);
            else if (p.act == ACT_SIG) v = 1.f / (1.f + expf(-v));
            p.out[(long)m * p.Cout + n] = v;
        }
    }
}

__global__ void up2_add_kernel(float* dst, const float* src, int H, int W, int total) {
    int i = blockIdx.x * blockDim.x + threadIdx.x;
    if (i >= total) return;
    int c = i & 255;
    int t = i >> 8;
    int w = t % W;
    t /= W;
    int h = t % H;
    int n = t / H;
    int Hs = H >> 1;
    int Ws = W >> 1;
    dst[i] += src[((((long)n * Hs + (h >> 1)) * Ws + (w >> 1)) << 8) + c];
}

__global__ void roi_pool_kernel(const float* fm, const float* rois, float* pooled) {
    int roi = blockIdx.x;
    int c = threadIdx.x;
    __shared__ int sy0[7], sy1[7], sx0[7], sx1[7];
    __shared__ float swy[7], swx[7];
    __shared__ int svy[7], svx[7];
    if (c == 0) {
        float y1 = rois[roi * 4 + 0] / 50.0f;
        float x1 = rois[roi * 4 + 1] / 50.0f;
        float y2 = rois[roi * 4 + 2] / 50.0f;
        float x2 = rois[roi * 4 + 3] / 50.0f;
        for (int i = 0; i < 7; i++) {
            float ys = y1 * 49.0f + (float)i * ((y2 - y1) * 49.0f / 6.0f);
            float xs = x1 * 49.0f + (float)i * ((x2 - x1) * 49.0f / 6.0f);
            float fy = floorf(ys);
            float fx = floorf(xs);
            int iy0 = min(max((int)fy, 0), 49);
            int ix0 = min(max((int)fx, 0), 49);
            sy0[i] = iy0;
            sy1[i] = min(iy0 + 1, 49);
            sx0[i] = ix0;
            sx1[i] = min(ix0 + 1, 49);
            swy[i] = ys - fy;
            swx[i] = xs - fx;
            svy[i] = (ys >= 0.0f && ys <= 49.0f) ? 1 : 0;
            svx[i] = (xs >= 0.0f && xs <= 49.0f) ? 1 : 0;
        }
    }
    __syncthreads();
    float acc = 0.f;
    for (int iy = 0; iy < 7; iy++) {
        if (!svy[iy]) continue;
        float wy = swy[iy];
        const float* r0 = fm + ((long)sy0[iy] * 50 << 8);
        const float* r1 = fm + ((long)sy1[iy] * 50 << 8);
        for (int ix = 0; ix < 7; ix++) {
            if (!svx[ix]) continue;
            float wx = swx[ix];
            float v00 = r0[(sx0[ix] << 8) + c];
            float v01 = r0[(sx1[ix] << 8) + c];
            float v10 = r1[(sx0[ix] << 8) + c];
            float v11 = r1[(sx1[ix] << 8) + c];
            acc += (1.f - wy) * (1.f - wx) * v00 + (1.f - wy) * wx * v01 +
                   wy * (1.f - wx) * v10 + wy * wx * v11;
        }
    }
    pooled[(roi << 8) + c] = acc * (1.0f / 49.0f);
}

__global__ void softmax8_kernel(float* x) {
    int r = blockIdx.x * blockDim.x + threadIdx.x;
    if (r >= 512) return;
    float* p = x + r * 8;
    float m = p[0];
#pragma unroll
    for (int i = 1; i < 8; i++) {
        m = fmaxf(m, p[i]);
    }
    float e[8];
    float s = 0.f;
#pragma unroll
    for (int i = 0; i < 8; i++) {
        e[i] = expf(p[i] - m);
        s += e[i];
    }
    float inv = 1.0f / s;
#pragma unroll
    for (int i = 0; i < 8; i++) {
        p[i] = e[i] * inv;
    }
}

__global__ void anchors_kernel(float* out) {
    int idx = blockIdx.x * blockDim.x + threadIdx.x;
    if (idx >= 159882) return;
    int lvl;
    int a;
    if (idx < 120000)      { lvl = 0; a = idx; }
    else if (idx < 150000) { lvl = 1; a = idx - 120000; }
    else if (idx < 157500) { lvl = 2; a = idx - 150000; }
    else if (idx < 159375) { lvl = 3; a = idx - 157500; }
    else                   { lvl = 4; a = idx - 159375; }
    const int   ws[5]  = {200, 100, 50, 25, 13};
    const float scl[5] = {32.f, 64.f, 128.f, 256.f, 512.f};
    const float st[5]  = {4.f, 8.f, 16.f, 32.f, 64.f};
    const float sq[3]  = {0.70710678118654752f, 1.0f, 1.41421356237309505f};
    int r = a % 3;
    int cell = a / 3;
    int w = ws[lvl];
    int y = cell / w;
    int x = cell - y * w;
    float sx = (float)x * st[lvl];
    float sy = (float)y * st[lvl];
    float s = scl[lvl];
    float hx = s * sq[r] * 0.5f;
    float hy = s / sq[r] * 0.5f;
    out[idx * 4 + 0] = sx - hx;
    out[idx * 4 + 1] = sy - hy;
    out[idx * 4 + 2] = sx + hx;
    out[idx * 4 + 3] = sy + hy;
}

// ---------------- host side ----------------
static void run_cvt(const float* src, __nv_bfloat16* hi, __nv_bfloat16* lo, long n) {
    int n4 = (int)(n >> 2);
    cvt_split<<<(n4 + 255) / 256, 256>>>(src, hi, lo, n4);
}

static void run_conv2(const __nv_bfloat16* aH, const __nv_bfloat16* aL,
                      const __nv_bfloat16* wH, const __nv_bfloat16* wL,
                      const float* bias, float* out,
                      int Nb, int Hin, int Win, int logCin,
                      int Hout, int Wout, int Cout,
                      int KW, int KH, int stride, int pad, int act) {
    Conv2Params p;
    p.aHi = aH;
    p.aLo = aL;
    p.wHi = wH;
    p.wLo = wL;
    p.bias = bias;
    p.out = out;
    p.Hin = Hin;
    p.Win = Win;
    p.logCin = logCin;
    p.Hout = Hout;
    p.Wout = Wout;
    p.Cout = Cout;
    p.M = Nb * Hout * Wout;
    p.KW = KW;
    p.stride = stride;
    p.pad = pad;
    p.Ktot = (KH * KW) << logCin;
    p.act = act;
    dim3 grid((p.M + 127) / 128, Cout / 128);
    conv_wmma2<<<grid, 256, SMEM_DYN>>>(p);
}

static void run_conv(const float* in, const float* w, const float* b, float* out,
                     int Nb, int Hin, int Win, int logCin,
                     int Hout, int Wout, int Cout,
                     int KW, int KH, int stride, int pad, int act) {
    ConvParams p;
    p.in = in;
    p.w = w;
    p.bias = b;
    p.out = out;
    p.Hin = Hin;
    p.Win = Win;
    p.logCin = logCin;
    p.Hout = Hout;
    p.Wout = Wout;
    p.Cout = Cout;
    p.M = Nb * Hout * Wout;
    p.KW = KW;
    p.stride = stride;
    p.pad = pad;
    p.Ktot = (KH * KW) << logCin;
    p.act = act;
    dim3 grid((p.M + BM - 1) / BM, (Cout + BN - 1) / BN);
    conv_gemm<<<grid, 256>>>(p);
}

extern "C" void kernel_launch(void* const* d_in, const int* in_sizes, int n_in,
                              void* d_out, int out_size) {
    const float* feat2 = (const float*)d_in[0];
    const float* feat3 = (const float*)d_in[1];
    const float* feat4 = (const float*)d_in[2];
    const float* feat5 = (const float*)d_in[3];
    const float* rois  = (const float*)d_in[4];
    const float* lw2 = (const float*)d_in[5];
    const float* lb2 = (const float*)d_in[6];
    const float* lw3 = (const float*)d_in[7];
    const float* lb3 = (const float*)d_in[8];
    const float* lw4 = (const float*)d_in[9];
    const float* lb4 = (const float*)d_in[10];
    const float* lw5 = (const float*)d_in[11];
    const float* lb5 = (const float*)d_in[12];
    const float* fw  = (const float*)d_in[13];
    const float* fb  = (const float*)d_in[14];
    const float* p6w = (const float*)d_in[15];
    const float* p6b = (const float*)d_in[16];
    const float* rpnw = (const float*)d_in[17];
    const float* rpnb = (const float*)d_in[18];
    const float* clsw = (const float*)d_in[19];
    const float* clsb = (const float*)d_in[20];
    const float* regw = (const float*)d_in[21];
    const float* regb = (const float*)d_in[22];
    const float* fc1w = (const float*)d_in[23];
    const float* fc1b = (const float*)d_in[24];
    const float* fc2w = (const float*)d_in[25];
    const float* fc2b = (const float*)d_in[26];
    const float* hclsw = (const float*)d_in[27];
    const float* hclsb = (const float*)d_in[28];
    const float* hregw = (const float*)d_in[29];
    const float* hregb = (const float*)d_in[30];
    float* out = (float*)d_out;

    float* sc = 0;
    cudaGetSymbolAddress((void**)&sc, g_scratch);
    __nv_bfloat16* bs = 0;
    cudaGetSymbolAddress((void**)&bs, g_bscratch);

    float* m2 = sc + SC_M2;
    float* m3 = sc + SC_M3;
    float* m4 = sc + SC_M4;
    float* m5 = sc + SC_M5;
    float* p2 = sc + SC_P2;
    float* p3 = sc + SC_P3;
    float* p4 = sc + SC_P4;
    float* p5 = sc + SC_P5;
    float* p6 = sc + SC_P6;
    float* rbuf = sc + SC_R;
    float* pooled = sc + SC_POOL;
    float* fc1 = sc + SC_FC1;
    float* fc2 = sc + SC_FC2;

    // convert weights + input features to bf16 hi/lo
    run_cvt(lw2, bs + B_WL2H, bs + B_WL2L, 65536L);
    run_cvt(lw3, bs + B_WL3H, bs + B_WL3L, 131072L);
    run_cvt(lw4, bs + B_WL4H, bs + B_WL4L, 262144L);
    run_cvt(lw5, bs + B_WL5H, bs + B_WL5L, 524288L);
    run_cvt(fw,  bs + B_WFWH, bs + B_WFWL, 2359296L);
    run_cvt(p6w, bs + B_WP6H, bs + B_WP6L, 589824L);
    run_cvt(rpnw, bs + B_WRPNH, bs + B_WRPNL, 1179648L);
    run_cvt(fc1w, bs + B_WFC1H, bs + B_WFC1L, 262144L);
    run_cvt(fc2w, bs + B_WFC2H, bs + B_WFC2L, 1048576L);
    run_cvt(feat2, bs + B_F2H, bs + B_F2L, 20480000L);
    run_cvt(feat3, bs + B_F3H, bs + B_F3L, 10240000L);
    run_cvt(feat4, bs + B_F4H, bs + B_F4L, 5120000L);
    run_cvt(feat5, bs + B_F5H, bs + B_F5L, 2560000L);

    // laterals (1x1) + top-down
    run_conv2(bs + B_F5H, bs + B_F5L, bs + B_WL5H, bs + B_WL5L, lb5, m5,
              2, 25, 25, 11, 25, 25, 256, 1, 1, 1, 0, ACT_NONE);
    run_conv2(bs + B_F4H, bs + B_F4L, bs + B_WL4H, bs + B_WL4L, lb4, m4,
              2, 50, 50, 10, 50, 50, 256, 1, 1, 1, 0, ACT_NONE);
    {
        int tot = 2 * 50 * 50 * 256;
        up2_add_kernel<<<(tot + 255) / 256, 256>>>(m4, m5, 50, 50, tot);
    }
    run_conv2(bs + B_F3H, bs + B_F3L, bs + B_WL3H, bs + B_WL3L, lb3, m3,
              2, 100, 100, 9, 100, 100, 256, 1, 1, 1, 0, ACT_NONE);
    {
        int tot = 2 * 100 * 100 * 256;
        up2_add_kernel<<<(tot + 255) / 256, 256>>>(m3, m4, 100, 100, tot);
    }
    run_conv2(bs + B_F2H, bs + B_F2L, bs + B_WL2H, bs + B_WL2L, lb2, m2,
              2, 200, 200, 8, 200, 200, 256, 1, 1, 1, 0, ACT_NONE);
    {
        int tot = 2 * 200 * 200 * 256;
        up2_add_kernel<<<(tot + 255) / 256, 256>>>(m2, m3, 200, 200, tot);
    }

    run_cvt(m5, bs + B_M5H, bs + B_M5L, 320000L);
    run_cvt(m4, bs + B_M4H, bs + B_M4L, 1280000L);
    run_cvt(m3, bs + B_M3H, bs + B_M3L, 5120000L);
    run_cvt(m2, bs + B_M2H, bs + B_M2L, 20480000L);

    // FPN 3x3 smoothing convs
    run_conv2(bs + B_M2H, bs + B_M2L, bs + B_WFWH + 0L * 589824L, bs + B_WFWL + 0L * 589824L,
              fb + 0, p2, 2, 200, 200, 8, 200, 200, 256, 3, 3, 1, 1, ACT_NONE);
    run_conv2(bs + B_M3H, bs + B_M3L, bs + B_WFWH + 1L * 589824L, bs + B_WFWL + 1L * 589824L,
              fb + 256, p3, 2, 100, 100, 8, 100, 100, 256, 3, 3, 1, 1, ACT_NONE);
    run_conv2(bs + B_M4H, bs + B_M4L, bs + B_WFWH + 2L * 589824L, bs + B_WFWL + 2L * 589824L,
              fb + 512, p4, 2, 50, 50, 8, 50, 50, 256, 3, 3, 1, 1, ACT_NONE);
    run_conv2(bs + B_M5H, bs + B_M5L, bs + B_WFWH + 3L * 589824L, bs + B_WFWL + 3L * 589824L,
              fb + 768, p5, 2, 25, 25, 8, 25, 25, 256, 3, 3, 1, 1, ACT_NONE);
    run_cvt(p5, bs + B_P5H, bs + B_P5L, 320000L);
    run_conv2(bs + B_P5H, bs + B_P5L, bs + B_WP6H, bs + B_WP6L, p6b, p6,
              2, 25, 25, 8, 13, 13, 256, 3, 3, 2, 1, ACT_NONE);

    run_cvt(p2, bs + B_P2H, bs + B_P2L, 20480000L);
    run_cvt(p3, bs + B_P3H, bs + B_P3L, 5120000L);
    run_cvt(p4, bs + B_P4H, bs + B_P4L, 1280000L);
    run_cvt(p6, bs + B_P6H, bs + B_P6L, 86528L);

    // RPN heads per level
    struct Lv { long ph; long pl; const float* pf; int H; int W; long co; long ro; };
    Lv lv[5] = {
        {B_P2H, B_P2L, p2, 200, 200, OFF_CLS2, OFF_REG2},
        {B_P3H, B_P3L, p3, 100, 100, OFF_CLS3, OFF_REG3},
        {B_P4H, B_P4L, p4,  50,  50, OFF_CLS4, OFF_REG4},
        {B_P5H, B_P5L, p5,  25,  25, OFF_CLS5, OFF_REG5},
        {B_P6H, B_P6L, p6,  13,  13, OFF_CLS6, OFF_REG6}
    };
    for (int i = 0; i < 5; i++) {
        run_conv2(bs + lv[i].ph, bs + lv[i].pl, bs + B_WRPNH, bs + B_WRPNL, rpnb, rbuf,
                  2, lv[i].H, lv[i].W, 8, lv[i].H, lv[i].W, 512, 3, 3, 1, 1, ACT_RELU);
        run_conv(rbuf, clsw, clsb, out + lv[i].co, 2, lv[i].H, lv[i].W, 9,
                 lv[i].H, lv[i].W, 3, 1, 1, 1, 0, ACT_SIG);
        run_conv(rbuf, regw, regb, out + lv[i].ro, 2, lv[i].H, lv[i].W, 9,
                 lv[i].H, lv[i].W, 12, 1, 1, 1, 0, ACT_NONE);
    }

    // RoI head
    roi_pool_kernel<<<512, 256>>>(p4, rois, pooled);
    run_cvt(pooled, bs + B_POOLH, bs + B_POOLL, 131072L);
    run_conv2(bs + B_POOLH, bs + B_POOLL, bs + B_WFC1H, bs + B_WFC1L, fc1b, fc1,
              1, 512, 1, 8, 512, 1, 1024, 1, 1, 1, 0, ACT_RELU);
    run_cvt(fc1, bs + B_FC1H, bs + B_FC1L, 524288L);
    run_conv2(bs + B_FC1H, bs + B_FC1L, bs + B_WFC2H, bs + B_WFC2L, fc2b, fc2,
              1, 512, 1, 10, 512, 1, 1024, 1, 1, 1, 0, ACT_RELU);
    run_cvt(fc2, bs + B_FC2H, bs + B_FC2L, 524288L);
    run_conv(fc2, hclsw, hclsb, out + OFF_ROICLS, 1, 512, 1, 10, 512, 1, 8, 1, 1, 1, 0, ACT_NONE);
    softmax8_kernel<<<2, 256>>>(out + OFF_ROICLS);
    run_conv(fc2, hregw, hregb, out + OFF_ROIREG, 1, 512, 1, 10, 512, 1, 32, 1, 1, 1, 0, ACT_NONE);

    // anchors
    anchors_kernel<<<(159882 + 255) / 256, 256>>>(out + OFF_ANCH);
}

// round 12
// speedup vs baseline: 2.4726x; 1.0452x over previous
#include <cuda_runtime.h>
#include <cuda_bf16.h>
#include <cuda_pipeline.h>
#include <mma.h>
#include <math.h>

using namespace nvcuda;

#define ACT_NONE 0
#define ACT_RELU 1
#define ACT_SIG  2

#define BM 128
#define BN 128
#define BKC 8

#define A_STR 24
#define B_STR 136
#define NSTAGE 4
#define A_ST_ELEM 3072
#define B_ST_ELEM 2176
#define SMEM_DYN 83968

// ---------------- fp32 scratch ----------------
#define SC_M2     0L
#define SC_M3     (SC_M2 + 20480000L)
#define SC_M4     (SC_M3 + 5120000L)
#define SC_M5     (SC_M4 + 1280000L)
#define SC_P2     (SC_M5 + 320000L)
#define SC_P3     (SC_P2 + 20480000L)
#define SC_P4     (SC_P3 + 5120000L)
#define SC_P5     (SC_P4 + 1280000L)
#define SC_P6     (SC_P5 + 320000L)
#define SC_R      (SC_P6 + 86528L)
#define SC_POOL   (SC_R + 40960000L)
#define SC_FC1    (SC_POOL + 131072L)
#define SC_FC2    (SC_FC1 + 524288L)
#define SC_TOTAL  (SC_FC2 + 524288L)

__device__ __align__(16) float g_scratch[SC_TOTAL];

// ---------------- bf16 hi/lo scratch ----------------
#define B_F2H 0L
#define B_F2L (B_F2H + 20480000L)
#define B_F3H (B_F2L + 20480000L)
#define B_F3L (B_F3H + 10240000L)
#define B_F4H (B_F3L + 10240000L)
#define B_F4L (B_F4H + 5120000L)
#define B_F5H (B_F4L + 5120000L)
#define B_F5L (B_F5H + 2560000L)
#define B_M2H (B_F5L + 2560000L)
#define B_M2L (B_M2H + 20480000L)
#define B_M3H (B_M2L + 20480000L)
#define B_M3L (B_M3H + 5120000L)
#define B_M4H (B_M3L + 5120000L)
#define B_M4L (B_M4H + 1280000L)
#define B_M5H (B_M4L + 1280000L)
#define B_M5L (B_M5H + 320000L)
#define B_P2H (B_M5L + 320000L)
#define B_P2L (B_P2H + 20480000L)
#define B_P3H (B_P2L + 20480000L)
#define B_P3L (B_P3H + 5120000L)
#define B_P4H (B_P3L + 5120000L)
#define B_P4L (B_P4H + 1280000L)
#define B_P5H (B_P4L + 1280000L)
#define B_P5L (B_P5H + 320000L)
#define B_P6H (B_P5L + 320000L)
#define B_P6L (B_P6H + 86528L)
#define B_POOLH (B_P6L + 86528L)
#define B_POOLL (B_POOLH + 131072L)
#define B_FC1H (B_POOLL + 131072L)
#define B_FC1L (B_FC1H + 524288L)
#define B_FC2H (B_FC1L + 524288L)
#define B_FC2L (B_FC2H + 524288L)
#define B_WL2H (B_FC2L + 524288L)
#define B_WL2L (B_WL2H + 65536L)
#define B_WL3H (B_WL2L + 65536L)
#define B_WL3L (B_WL3H + 131072L)
#define B_WL4H (B_WL3L + 131072L)
#define B_WL4L (B_WL4H + 262144L)
#define B_WL5H (B_WL4L + 262144L)
#define B_WL5L (B_WL5H + 524288L)
#define B_WFWH (B_WL5L + 524288L)
#define B_WFWL (B_WFWH + 2359296L)
#define B_WP6H (B_WFWL + 2359296L)
#define B_WP6L (B_WP6H + 589824L)
#define B_WRPNH (B_WP6L + 589824L)
#define B_WRPNL (B_WRPNH + 1179648L)
#define B_WFC1H (B_WRPNL + 1179648L)
#define B_WFC1L (B_WFC1H + 262144L)
#define B_WFC2H (B_WFC1L + 262144L)
#define B_WFC2L (B_WFC2H + 1048576L)
#define B_TOTAL (B_WFC2L + 1048576L)

__device__ __align__(16) __nv_bfloat16 g_bscratch[B_TOTAL];

// ---------------- output offsets ----------------
#define OFF_CLS2 0L
#define OFF_CLS3 240000L
#define OFF_CLS4 300000L
#define OFF_CLS5 315000L
#define OFF_CLS6 318750L
#define OFF_REG2 319764L
#define OFF_REG3 1279764L
#define OFF_REG4 1519764L
#define OFF_REG5 1579764L
#define OFF_REG6 1594764L
#define OFF_ROICLS 1598820L
#define OFF_ROIREG 1602916L
#define OFF_ANCH   1619300L

struct ConvParams {
    const float* in;
    const float* w;
    const float* bias;
    float* out;
    int Hin, Win, logCin;
    int Hout, Wout, Cout;
    int M;
    int KW, stride, pad, Ktot, act;
};

struct Conv2Params {
    const __nv_bfloat16* aHi;
    const __nv_bfloat16* aLo;
    const __nv_bfloat16* wHi;
    const __nv_bfloat16* wLo;
    const float* bias;
    float* out;
    int Hin, Win, logCin;
    int Hout, Wout, Cout;
    int M;
    int KW, stride, pad, Ktot, act;
};

__device__ __forceinline__ void split_store(__nv_bfloat16* hi, __nv_bfloat16* lo, float4 v) {
    __nv_bfloat16 h0 = __float2bfloat16_rn(v.x);
    __nv_bfloat16 h1 = __float2bfloat16_rn(v.y);
    __nv_bfloat16 h2 = __float2bfloat16_rn(v.z);
    __nv_bfloat16 h3 = __float2bfloat16_rn(v.w);
    __nv_bfloat16 l0 = __float2bfloat16_rn(v.x - __bfloat162float(h0));
    __nv_bfloat16 l1 = __float2bfloat16_rn(v.y - __bfloat162float(h1));
    __nv_bfloat16 l2 = __float2bfloat16_rn(v.z - __bfloat162float(h2));
    __nv_bfloat16 l3 = __float2bfloat16_rn(v.w - __bfloat162float(h3));
    reinterpret_cast<__nv_bfloat162*>(hi)[0] = __nv_bfloat162(h0, h1);
    reinterpret_cast<__nv_bfloat162*>(hi)[1] = __nv_bfloat162(h2, h3);
    reinterpret_cast<__nv_bfloat162*>(lo)[0] = __nv_bfloat162(l0, l1);
    reinterpret_cast<__nv_bfloat162*>(lo)[1] = __nv_bfloat162(l2, l3);
}

__global__ void cvt_split(const float* src, __nv_bfloat16* hi, __nv_bfloat16* lo, int n4) {
    int i = blockIdx.x * blockDim.x + threadIdx.x;
    if (i >= n4) return;
    float4 v = reinterpret_cast<const float4*>(src)[i];
    split_store(hi + (long)i * 4, lo + (long)i * 4, v);
}

// issue one 16-k stage of cp.async loads
__device__ __forceinline__ void issue_stage(
    const Conv2Params& p, int kb, int st,
    __nv_bfloat16* AsH, __nv_bfloat16* AsL,
    __nv_bfloat16* BsH, __nv_bfloat16* BsL,
    long aBase, bool am_ok, int aoh, int aow,
    int arow, int kseg, int krow, int cseg, int n0)
{
    int k0 = kb + kseg;
    int tap = k0 >> p.logCin;
    int ci = k0 & ((1 << p.logCin) - 1);
    int dy = tap / p.KW;
    int dx = tap - dy * p.KW;
    int ih = aoh * p.stride + dy - p.pad;
    int iw = aow * p.stride + dx - p.pad;
    bool ok = am_ok && (unsigned)ih < (unsigned)p.Hin && (unsigned)iw < (unsigned)p.Win;
    size_t zf = ok ? 0 : 16;
    long src = ok ? (aBase + (((long)ih * p.Win + iw) << p.logCin) + ci) : 0;
    __pipeline_memcpy_async(AsH + st * A_ST_ELEM + arow * A_STR + kseg, p.aHi + src, 16, zf);
    __pipeline_memcpy_async(AsL + st * A_ST_ELEM + arow * A_STR + kseg, p.aLo + src, 16, zf);
    long wsrc = (long)(kb + krow) * p.Cout + n0 + cseg;
    __pipeline_memcpy_async(BsH + st * B_ST_ELEM + krow * B_STR + cseg, p.wHi + wsrc, 16, (size_t)0);
    __pipeline_memcpy_async(BsL + st * B_ST_ELEM + krow * B_STR + cseg, p.wLo + wsrc, 16, (size_t)0);
}

__global__ __launch_bounds__(256, 2) void conv_wmma2(Conv2Params p) {
    extern __shared__ __nv_bfloat16 smem[];
    __nv_bfloat16* AsH = smem;
    __nv_bfloat16* AsL = smem + NSTAGE * A_ST_ELEM;
    __nv_bfloat16* BsH = smem + 2 * NSTAGE * A_ST_ELEM;
    __nv_bfloat16* BsL = smem + 2 * NSTAGE * A_ST_ELEM + NSTAGE * B_ST_ELEM;

    const int tid = threadIdx.x;
    const int lane = tid & 31;
    const int warp = tid >> 5;
    const int wm = warp >> 2;
    const int wn = warp & 3;
    const int m0 = blockIdx.x * 128;
    const int n0 = blockIdx.y * 128;

    const int arow = tid >> 1;
    const int kseg = (tid & 1) << 3;
    const int krow = tid >> 4;
    const int cseg = (tid & 15) << 3;

    const int am = m0 + arow;
    const bool am_ok = am < p.M;
    int aoh = 0;
    int aow = 0;
    long aBase = 0;
    if (am_ok) {
        int hw = p.Hout * p.Wout;
        int an = am / hw;
        int r = am - an * hw;
        aoh = r / p.Wout;
        aow = r - aoh * p.Wout;
        aBase = ((long)an * p.Hin * p.Win) << p.logCin;
    }

    wmma::fragment<wmma::accumulator, 16, 16, 16, float> acc[4][2];
#pragma unroll
    for (int mt = 0; mt < 4; mt++) {
#pragma unroll
        for (int nt = 0; nt < 2; nt++) {
            wmma::fill_fragment(acc[mt][nt], 0.0f);
        }
    }

    const int nK = p.Ktot >> 4;

    // prologue: issue stages 0..NSTAGE-2
#pragma unroll
    for (int s = 0; s < NSTAGE - 1; s++) {
        if (s < nK) {
            issue_stage(p, s << 4, s, AsH, AsL, BsH, BsL,
                        aBase, am_ok, aoh, aow, arow, kseg, krow, cseg, n0);
        }
        __pipeline_commit();
    }

    for (int kt = 0; kt < nK; kt++) {
        __pipeline_wait_prior(NSTAGE - 2);
        __syncthreads();

        const int st = kt % NSTAGE;
        const __nv_bfloat16* aH = AsH + st * A_ST_ELEM;
        const __nv_bfloat16* aL = AsL + st * A_ST_ELEM;
        const __nv_bfloat16* bH = BsH + st * B_ST_ELEM;
        const __nv_bfloat16* bL = BsL + st * B_ST_ELEM;

        wmma::fragment<wmma::matrix_b, 16, 16, 16, __nv_bfloat16, wmma::row_major> fBH[2];
        wmma::fragment<wmma::matrix_b, 16, 16, 16, __nv_bfloat16, wmma::row_major> fBL[2];
#pragma unroll
        for (int nt = 0; nt < 2; nt++) {
            int bc = wn * 32 + nt * 16;
            wmma::load_matrix_sync(fBH[nt], bH + bc, B_STR);
            wmma::load_matrix_sync(fBL[nt], bL + bc, B_STR);
        }
#pragma unroll
        for (int mt = 0; mt < 4; mt++) {
            wmma::fragment<wmma::matrix_a, 16, 16, 16, __nv_bfloat16, wmma::row_major> fAH;
            wmma::fragment<wmma::matrix_a, 16, 16, 16, __nv_bfloat16, wmma::row_major> fAL;
            int row = wm * 64 + mt * 16;
            wmma::load_matrix_sync(fAH, aH + row * A_STR, A_STR);
            wmma::load_matrix_sync(fAL, aL + row * A_STR, A_STR);
#pragma unroll
            for (int nt = 0; nt < 2; nt++) {
                wmma::mma_sync(acc[mt][nt], fAH, fBH[nt], acc[mt][nt]);
                wmma::mma_sync(acc[mt][nt], fAH, fBL[nt], acc[mt][nt]);
                wmma::mma_sync(acc[mt][nt], fAL, fBH[nt], acc[mt][nt]);
            }
        }

        // issue stage kt+NSTAGE-1 (its buffer was last computed at kt-1,
        // separated from here by the syncthreads at this iteration's start)
        int kn = kt + NSTAGE - 1;
        if (kn < nK) {
            issue_stage(p, kn << 4, kn % NSTAGE, AsH, AsL, BsH, BsL,
                        aBase, am_ok, aoh, aow, arow, kseg, krow, cseg, n0);
        }
        __pipeline_commit();
    }

    __syncthreads();

    // epilogue: stage accumulators through smem (reuse stage buffers)
    float* Cs = reinterpret_cast<float*>(smem);
    float* cwarp = Cs + warp * 256;
#pragma unroll
    for (int mt = 0; mt < 4; mt++) {
#pragma unroll
        for (int nt = 0; nt < 2; nt++) {
            wmma::store_matrix_sync(cwarp, acc[mt][nt], 16, wmma::mem_row_major);
            __syncwarp();
#pragma unroll
            for (int e = 0; e < 8; e++) {
                int idx = e * 32 + lane;
                int r = idx >> 4;
                int cc = idx & 15;
                int m = m0 + wm * 64 + mt * 16 + r;
                int n = n0 + wn * 32 + nt * 16 + cc;
                if (m < p.M) {
                    float v = cwarp[idx] + p.bias[n];
                    if (p.act == ACT_RELU) v = fmaxf(v, 0.f);
                    p.out[(long)m * p.Cout + n] = v;
                }
            }
            __syncwarp();
        }
    }
}

// ======================= fp32 fallback GEMM (small heads) =======================
__global__ __launch_bounds__(256) void conv_gemm(ConvParams p) {
    __shared__ float As[BKC][BM];
    __shared__ float Bs[BKC][BN];
    const int tid = threadIdx.x;
    const int m0 = blockIdx.x * BM;
    const int n0 = blockIdx.y * BN;

    const int arow = tid >> 1;
    const int kq = (tid & 1) << 2;
    const int am = m0 + arow;
    const bool am_ok = am < p.M;
    int aoh = 0;
    int aow = 0;
    const float* abase = p.in;
    if (am_ok) {
        int hw = p.Hout * p.Wout;
        int an = am / hw;
        int r = am - an * hw;
        aoh = r / p.Wout;
        aow = r - aoh * p.Wout;
        abase = p.in + (((long)an * p.Hin * p.Win) << p.logCin);
    }
    const int brow = tid >> 5;
    const int bcol = (tid & 31) << 2;
    const bool bvec = ((p.Cout & 3) == 0) && (n0 + BN <= p.Cout);
    const int cmask = (1 << p.logCin) - 1;

    float acc[8][8];
#pragma unroll
    for (int i = 0; i < 8; i++) {
#pragma unroll
        for (int j = 0; j < 8; j++) {
            acc[i][j] = 0.f;
        }
    }

    const int ty = tid >> 4;
    const int tx = tid & 15;

    for (int kb = 0; kb < p.Ktot; kb += BKC) {
        float4 av = make_float4(0.f, 0.f, 0.f, 0.f);
        if (am_ok) {
            int k0 = kb + kq;
            int tap = k0 >> p.logCin;
            int ci = k0 & cmask;
            int dy = tap / p.KW;
            int dx = tap - dy * p.KW;
            int ih = aoh * p.stride + dy - p.pad;
            int iw = aow * p.stride + dx - p.pad;
            if ((unsigned)ih < (unsigned)p.Hin && (unsigned)iw < (unsigned)p.Win) {
                av = *reinterpret_cast<const float4*>(
                    abase + (((long)ih * p.Win + iw) << p.logCin) + ci);
            }
        }
        As[kq + 0][arow] = av.x;
        As[kq + 1][arow] = av.y;
        As[kq + 2][arow] = av.z;
        As[kq + 3][arow] = av.w;
        {
            int kB = kb + brow;
            const float* wp = p.w + (long)kB * p.Cout + n0 + bcol;
            float4 bv;
            if (bvec) {
                bv = *reinterpret_cast<const float4*>(wp);
            } else {
                int nb = n0 + bcol;
                bv.x = (nb + 0 < p.Cout) ? wp[0] : 0.f;
                bv.y = (nb + 1 < p.Cout) ? wp[1] : 0.f;
                bv.z = (nb + 2 < p.Cout) ? wp[2] : 0.f;
                bv.w = (nb + 3 < p.Cout) ? wp[3] : 0.f;
            }
            *reinterpret_cast<float4*>(&Bs[brow][bcol]) = bv;
        }
        __syncthreads();
#pragma unroll
        for (int kk = 0; kk < BKC; kk++) {
            float4 a0 = *reinterpret_cast<const float4*>(&As[kk][ty << 3]);
            float4 a1 = *reinterpret_cast<const float4*>(&As[kk][(ty << 3) + 4]);
            float4 b0 = *reinterpret_cast<const float4*>(&Bs[kk][tx << 3]);
            float4 b1 = *reinterpret_cast<const float4*>(&Bs[kk][(tx << 3) + 4]);
            float ra[8] = {a0.x, a0.y, a0.z, a0.w, a1.x, a1.y, a1.z, a1.w};
            float rb[8] = {b0.x, b0.y, b0.z, b0.w, b1.x, b1.y, b1.z, b1.w};
#pragma unroll
            for (int i = 0; i < 8; i++) {
#pragma unroll
                for (int j = 0; j < 8; j++) {
                    acc[i][j] += ra[i] * rb[j];
                }
            }
        }
        __syncthreads();
    }

#pragma unroll
    for (int i = 0; i < 8; i++) {
        int m = m0 + (ty << 3) + i;
        if (m >= p.M) continue;
#pragma unroll
        for (int j = 0; j < 8; j++) {
            int n = n0 + (tx << 3) + j;
            if (n >= p.Cout) continue;
            float v = acc[i][j] + p.bias[n];
            if (p.act == ACT_RELU) v = fmaxf(v, 0.f);
            else if (p.act == ACT_SIG) v = 1.f / (1.f + expf(-v));
            p.out[(long)m * p.Cout + n] = v;
        }
    }
}

__global__ void up2_add_kernel(float* dst, const float* src, int H, int W, int total) {
    int i = blockIdx.x * blockDim.x + threadIdx.x;
    if (i >= total) return;
    int c = i & 255;
    int t = i >> 8;
    int w = t % W;
    t /= W;
    int h = t % H;
    int n = t / H;
    int Hs = H >> 1;
    int Ws = W >> 1;
    dst[i] += src[((((long)n * Hs + (h >> 1)) * Ws + (w >> 1)) << 8) + c];
}

__global__ void roi_pool_kernel(const float* fm, const float* rois, float* pooled) {
    int roi = blockIdx.x;
    int c = threadIdx.x;
    __shared__ int sy0[7], sy1[7], sx0[7], sx1[7];
    __shared__ float swy[7], swx[7];
    __shared__ int svy[7], svx[7];
    if (c == 0) {
        float y1 = rois[roi * 4 + 0] / 50.0f;
        float x1 = rois[roi * 4 + 1] / 50.0f;
        float y2 = rois[roi * 4 + 2] / 50.0f;
        float x2 = rois[roi * 4 + 3] / 50.0f;
        for (int i = 0; i < 7; i++) {
            float ys = y1 * 49.0f + (float)i * ((y2 - y1) * 49.0f / 6.0f);
            float xs = x1 * 49.0f + (float)i * ((x2 - x1) * 49.0f / 6.0f);
            float fy = floorf(ys);
            float fx = floorf(xs);
            int iy0 = min(max((int)fy, 0), 49);
            int ix0 = min(max((int)fx, 0), 49);
            sy0[i] = iy0;
            sy1[i] = min(iy0 + 1, 49);
            sx0[i] = ix0;
            sx1[i] = min(ix0 + 1, 49);
            swy[i] = ys - fy;
            swx[i] = xs - fx;
            svy[i] = (ys >= 0.0f && ys <= 49.0f) ? 1 : 0;
            svx[i] = (xs >= 0.0f && xs <= 49.0f) ? 1 : 0;
        }
    }
    __syncthreads();
    float acc = 0.f;
    for (int iy = 0; iy < 7; iy++) {
        if (!svy[iy]) continue;
        float wy = swy[iy];
        const float* r0 = fm + ((long)sy0[iy] * 50 << 8);
        const float* r1 = fm + ((long)sy1[iy] * 50 << 8);
        for (int ix = 0; ix < 7; ix++) {
            if (!svx[ix]) continue;
            float wx = swx[ix];
            float v00 = r0[(sx0[ix] << 8) + c];
            float v01 = r0[(sx1[ix] << 8) + c];
            float v10 = r1[(sx0[ix] << 8) + c];
            float v11 = r1[(sx1[ix] << 8) + c];
            acc += (1.f - wy) * (1.f - wx) * v00 + (1.f - wy) * wx * v01 +
                   wy * (1.f - wx) * v10 + wy * wx * v11;
        }
    }
    pooled[(roi << 8) + c] = acc * (1.0f / 49.0f);
}

__global__ void softmax8_kernel(float* x) {
    int r = blockIdx.x * blockDim.x + threadIdx.x;
    if (r >= 512) return;
    float* p = x + r * 8;
    float m = p[0];
#pragma unroll
    for (int i = 1; i < 8; i++) {
        m = fmaxf(m, p[i]);
    }
    float e[8];
    float s = 0.f;
#pragma unroll
    for (int i = 0; i < 8; i++) {
        e[i] = expf(p[i] - m);
        s += e[i];
    }
    float inv = 1.0f / s;
#pragma unroll
    for (int i = 0; i < 8; i++) {
        p[i] = e[i] * inv;
    }
}

__global__ void anchors_kernel(float* out) {
    int idx = blockIdx.x * blockDim.x + threadIdx.x;
    if (idx >= 159882) return;
    int lvl;
    int a;
    if (idx < 120000)      { lvl = 0; a = idx; }
    else if (idx < 150000) { lvl = 1; a = idx - 120000; }
    else if (idx < 157500) { lvl = 2; a = idx - 150000; }
    else if (idx < 159375) { lvl = 3; a = idx - 157500; }
    else                   { lvl = 4; a = idx - 159375; }
    const int   ws[5]  = {200, 100, 50, 25, 13};
    const float scl[5] = {32.f, 64.f, 128.f, 256.f, 512.f};
    const float st[5]  = {4.f, 8.f, 16.f, 32.f, 64.f};
    const float sq[3]  = {0.70710678118654752f, 1.0f, 1.41421356237309505f};
    int r = a % 3;
    int cell = a / 3;
    int w = ws[lvl];
    int y = cell / w;
    int x = cell - y * w;
    float sx = (float)x * st[lvl];
    float sy = (float)y * st[lvl];
    float s = scl[lvl];
    float hx = s * sq[r] * 0.5f;
    float hy = s / sq[r] * 0.5f;
    out[idx * 4 + 0] = sx - hx;
    out[idx * 4 + 1] = sy - hy;
    out[idx * 4 + 2] = sx + hx;
    out[idx * 4 + 3] = sy + hy;
}

// ---------------- host side ----------------
static void run_cvt(const float* src, __nv_bfloat16* hi, __nv_bfloat16* lo, long n) {
    int n4 = (int)(n >> 2);
    cvt_split<<<(n4 + 255) / 256, 256>>>(src, hi, lo, n4);
}

static void run_conv2(const __nv_bfloat16* aH, const __nv_bfloat16* aL,
                      const __nv_bfloat16* wH, const __nv_bfloat16* wL,
                      const float* bias, float* out,
                      int Nb, int Hin, int Win, int logCin,
                      int Hout, int Wout, int Cout,
                      int KW, int KH, int stride, int pad, int act) {
    cudaFuncSetAttribute(conv_wmma2, cudaFuncAttributeMaxDynamicSharedMemorySize, SMEM_DYN);
    Conv2Params p;
    p.aHi = aH;
    p.aLo = aL;
    p.wHi = wH;
    p.wLo = wL;
    p.bias = bias;
    p.out = out;
    p.Hin = Hin;
    p.Win = Win;
    p.logCin = logCin;
    p.Hout = Hout;
    p.Wout = Wout;
    p.Cout = Cout;
    p.M = Nb * Hout * Wout;
    p.KW = KW;
    p.stride = stride;
    p.pad = pad;
    p.Ktot = (KH * KW) << logCin;
    p.act = act;
    dim3 grid((p.M + 127) / 128, Cout / 128);
    conv_wmma2<<<grid, 256, SMEM_DYN>>>(p);
}

static void run_conv(const float* in, const float* w, const float* b, float* out,
                     int Nb, int Hin, int Win, int logCin,
                     int Hout, int Wout, int Cout,
                     int KW, int KH, int stride, int pad, int act) {
    ConvParams p;
    p.in = in;
    p.w = w;
    p.bias = b;
    p.out = out;
    p.Hin = Hin;
    p.Win = Win;
    p.logCin = logCin;
    p.Hout = Hout;
    p.Wout = Wout;
    p.Cout = Cout;
    p.M = Nb * Hout * Wout;
    p.KW = KW;
    p.stride = stride;
    p.pad = pad;
    p.Ktot = (KH * KW) << logCin;
    p.act = act;
    dim3 grid((p.M + BM - 1) / BM, (Cout + BN - 1) / BN);
    conv_gemm<<<grid, 256>>>(p);
}

extern "C" void kernel_launch(void* const* d_in, const int* in_sizes, int n_in,
                              void* d_out, int out_size) {
    const float* feat2 = (const float*)d_in[0];
    const float* feat3 = (const float*)d_in[1];
    const float* feat4 = (const float*)d_in[2];
    const float* feat5 = (const float*)d_in[3];
    const float* rois  = (const float*)d_in[4];
    const float* lw2 = (const float*)d_in[5];
    const float* lb2 = (const float*)d_in[6];
    const float* lw3 = (const float*)d_in[7];
    const float* lb3 = (const float*)d_in[8];
    const float* lw4 = (const float*)d_in[9];
    const float* lb4 = (const float*)d_in[10];
    const float* lw5 = (const float*)d_in[11];
    const float* lb5 = (const float*)d_in[12];
    const float* fw  = (const float*)d_in[13];
    const float* fb  = (const float*)d_in[14];
    const float* p6w = (const float*)d_in[15];
    const float* p6b = (const float*)d_in[16];
    const float* rpnw = (const float*)d_in[17];
    const float* rpnb = (const float*)d_in[18];
    const float* clsw = (const float*)d_in[19];
    const float* clsb = (const float*)d_in[20];
    const float* regw = (const float*)d_in[21];
    const float* regb = (const float*)d_in[22];
    const float* fc1w = (const float*)d_in[23];
    const float* fc1b = (const float*)d_in[24];
    const float* fc2w = (const float*)d_in[25];
    const float* fc2b = (const float*)d_in[26];
    const float* hclsw = (const float*)d_in[27];
    const float* hclsb = (const float*)d_in[28];
    const float* hregw = (const float*)d_in[29];
    const float* hregb = (const float*)d_in[30];
    float* out = (float*)d_out;

    float* sc = 0;
    cudaGetSymbolAddress((void**)&sc, g_scratch);
    __nv_bfloat16* bs = 0;
    cudaGetSymbolAddress((void**)&bs, g_bscratch);

    float* m2 = sc + SC_M2;
    float* m3 = sc + SC_M3;
    float* m4 = sc + SC_M4;
    float* m5 = sc + SC_M5;
    float* p2 = sc + SC_P2;
    float* p3 = sc + SC_P3;
    float* p4 = sc + SC_P4;
    float* p5 = sc + SC_P5;
    float* p6 = sc + SC_P6;
    float* rbuf = sc + SC_R;
    float* pooled = sc + SC_POOL;
    float* fc1 = sc + SC_FC1;
    float* fc2 = sc + SC_FC2;

    // convert weights + input features to bf16 hi/lo
    run_cvt(lw2, bs + B_WL2H, bs + B_WL2L, 65536L);
    run_cvt(lw3, bs + B_WL3H, bs + B_WL3L, 131072L);
    run_cvt(lw4, bs + B_WL4H, bs + B_WL4L, 262144L);
    run_cvt(lw5, bs + B_WL5H, bs + B_WL5L, 524288L);
    run_cvt(fw,  bs + B_WFWH, bs + B_WFWL, 2359296L);
    run_cvt(p6w, bs + B_WP6H, bs + B_WP6L, 589824L);
    run_cvt(rpnw, bs + B_WRPNH, bs + B_WRPNL, 1179648L);
    run_cvt(fc1w, bs + B_WFC1H, bs + B_WFC1L, 262144L);
    run_cvt(fc2w, bs + B_WFC2H, bs + B_WFC2L, 1048576L);
    run_cvt(feat2, bs + B_F2H, bs + B_F2L, 20480000L);
    run_cvt(feat3, bs + B_F3H, bs + B_F3L, 10240000L);
    run_cvt(feat4, bs + B_F4H, bs + B_F4L, 5120000L);
    run_cvt(feat5, bs + B_F5H, bs + B_F5L, 2560000L);

    // laterals (1x1) + top-down
    run_conv2(bs + B_F5H, bs + B_F5L, bs + B_WL5H, bs + B_WL5L, lb5, m5,
              2, 25, 25, 11, 25, 25, 256, 1, 1, 1, 0, ACT_NONE);
    run_conv2(bs + B_F4H, bs + B_F4L, bs + B_WL4H, bs + B_WL4L, lb4, m4,
              2, 50, 50, 10, 50, 50, 256, 1, 1, 1, 0, ACT_NONE);
    {
        int tot = 2 * 50 * 50 * 256;
        up2_add_kernel<<<(tot + 255) / 256, 256>>>(m4, m5, 50, 50, tot);
    }
    run_conv2(bs + B_F3H, bs + B_F3L, bs + B_WL3H, bs + B_WL3L, lb3, m3,
              2, 100, 100, 9, 100, 100, 256, 1, 1, 1, 0, ACT_NONE);
    {
        int tot = 2 * 100 * 100 * 256;
        up2_add_kernel<<<(tot + 255) / 256, 256>>>(m3, m4, 100, 100, tot);
    }
    run_conv2(bs + B_F2H, bs + B_F2L, bs + B_WL2H, bs + B_WL2L, lb2, m2,
              2, 200, 200, 8, 200, 200, 256, 1, 1, 1, 0, ACT_NONE);
    {
        int tot = 2 * 200 * 200 * 256;
        up2_add_kernel<<<(tot + 255) / 256, 256>>>(m2, m3, 200, 200, tot);
    }

    run_cvt(m5, bs + B_M5H, bs + B_M5L, 320000L);
    run_cvt(m4, bs + B_M4H, bs + B_M4L, 1280000L);
    run_cvt(m3, bs + B_M3H, bs + B_M3L, 5120000L);
    run_cvt(m2, bs + B_M2H, bs + B_M2L, 20480000L);

    // FPN 3x3 smoothing convs
    run_conv2(bs + B_M2H, bs + B_M2L, bs + B_WFWH + 0L * 589824L, bs + B_WFWL + 0L * 589824L,
              fb + 0, p2, 2, 200, 200, 8, 200, 200, 256, 3, 3, 1, 1, ACT_NONE);
    run_conv2(bs + B_M3H, bs + B_M3L, bs + B_WFWH + 1L * 589824L, bs + B_WFWL + 1L * 589824L,
              fb + 256, p3, 2, 100, 100, 8, 100, 100, 256, 3, 3, 1, 1, ACT_NONE);
    run_conv2(bs + B_M4H, bs + B_M4L, bs + B_WFWH + 2L * 589824L, bs + B_WFWL + 2L * 589824L,
              fb + 512, p4, 2, 50, 50, 8, 50, 50, 256, 3, 3, 1, 1, ACT_NONE);
    run_conv2(bs + B_M5H, bs + B_M5L, bs + B_WFWH + 3L * 589824L, bs + B_WFWL + 3L * 589824L,
              fb + 768, p5, 2, 25, 25, 8, 25, 25, 256, 3, 3, 1, 1, ACT_NONE);
    run_cvt(p5, bs + B_P5H, bs + B_P5L, 320000L);
    run_conv2(bs + B_P5H, bs + B_P5L, bs + B_WP6H, bs + B_WP6L, p6b, p6,
              2, 25, 25, 8, 13, 13, 256, 3, 3, 2, 1, ACT_NONE);

    run_cvt(p2, bs + B_P2H, bs + B_P2L, 20480000L);
    run_cvt(p3, bs + B_P3H, bs + B_P3L, 5120000L);
    run_cvt(p4, bs + B_P4H, bs + B_P4L, 1280000L);
    run_cvt(p6, bs + B_P6H, bs + B_P6L, 86528L);

    // RPN heads per level
    struct Lv { long ph; long pl; const float* pf; int H; int W; long co; long ro; };
    Lv lv[5] = {
        {B_P2H, B_P2L, p2, 200, 200, OFF_CLS2, OFF_REG2},
        {B_P3H, B_P3L, p3, 100, 100, OFF_CLS3, OFF_REG3},
        {B_P4H, B_P4L, p4,  50,  50, OFF_CLS4, OFF_REG4},
        {B_P5H, B_P5L, p5,  25,  25, OFF_CLS5, OFF_REG5},
        {B_P6H, B_P6L, p6,  13,  13, OFF_CLS6, OFF_REG6}
    };
    for (int i = 0; i < 5; i++) {
        run_conv2(bs + lv[i].ph, bs + lv[i].pl, bs + B_WRPNH, bs + B_WRPNL, rpnb, rbuf,
                  2, lv[i].H, lv[i].W, 8, lv[i].H, lv[i].W, 512, 3, 3, 1, 1, ACT_RELU);
        run_conv(rbuf, clsw, clsb, out + lv[i].co, 2, lv[i].H, lv[i].W, 9,
                 lv[i].H, lv[i].W, 3, 1, 1, 1, 0, ACT_SIG);
        run_conv(rbuf, regw, regb, out + lv[i].ro, 2, lv[i].H, lv[i].W, 9,
                 lv[i].H, lv[i].W, 12, 1, 1, 1, 0, ACT_NONE);
    }

    // RoI head
    roi_pool_kernel<<<512, 256>>>(p4, rois, pooled);
    run_cvt(pooled, bs + B_POOLH, bs + B_POOLL, 131072L);
    run_conv2(bs + B_POOLH, bs + B_POOLL, bs + B_WFC1H, bs + B_WFC1L, fc1b, fc1,
              1, 512, 1, 8, 512, 1, 1024, 1, 1, 1, 0, ACT_RELU);
    run_cvt(fc1, bs + B_FC1H, bs + B_FC1L, 524288L);
    run_conv2(bs + B_FC1H, bs + B_FC1L, bs + B_WFC2H, bs + B_WFC2L, fc2b, fc2,
              1, 512, 1, 10, 512, 1, 1024, 1, 1, 1, 0, ACT_RELU);
    run_cvt(fc2, bs + B_FC2H, bs + B_FC2L, 524288L);
    run_conv(fc2, hclsw, hclsb, out + OFF_ROICLS, 1, 512, 1, 10, 512, 1, 8, 1, 1, 1, 0, ACT_NONE);
    softmax8_kernel<<<2, 256>>>(out + OFF_ROICLS);
    run_conv(fc2, hregw, hregb, out + OFF_ROIREG, 1, 512, 1, 10, 512, 1, 32, 1, 1, 1, 0, ACT_NONE);

    // anchors
    anchors_kernel<<<(159882 + 255) / 256, 256>>>(out + OFF_ANCH);
}

// round 13
// speedup vs baseline: 2.9020x; 1.1737x over previous
#include <cuda_runtime.h>
#include <cuda_bf16.h>
#include <cuda_pipeline.h>
#include <mma.h>
#include <math.h>

using namespace nvcuda;

#define ACT_NONE 0
#define ACT_RELU 1
#define ACT_SIG  2

#define BM 128
#define BN 128
#define BKC 8

#define A_STR 24
#define B_STR 136
#define NSTAGE 4
#define A_ST_ELEM 3072
#define B_ST_ELEM 2176
#define SMEM_DYN 83968

// ---------------- fp32 scratch ----------------
#define SC_M2     0L
#define SC_M3     (SC_M2 + 20480000L)
#define SC_M4     (SC_M3 + 5120000L)
#define SC_M5     (SC_M4 + 1280000L)
#define SC_P4     (SC_M5 + 320000L)
#define SC_R      (SC_P4 + 1280000L)
#define SC_FC2    (SC_R + 40960000L)
#define SC_TOTAL  (SC_FC2 + 524288L)

__device__ __align__(16) float g_scratch[SC_TOTAL];

// ---------------- bf16 hi/lo scratch ----------------
#define B_F2H 0L
#define B_F2L (B_F2H + 20480000L)
#define B_F3H (B_F2L + 20480000L)
#define B_F3L (B_F3H + 10240000L)
#define B_F4H (B_F3L + 10240000L)
#define B_F4L (B_F4H + 5120000L)
#define B_F5H (B_F4L + 5120000L)
#define B_F5L (B_F5H + 2560000L)
#define B_M2H (B_F5L + 2560000L)
#define B_M2L (B_M2H + 20480000L)
#define B_M3H (B_M2L + 20480000L)
#define B_M3L (B_M3H + 5120000L)
#define B_M4H (B_M3L + 5120000L)
#define B_M4L (B_M4H + 1280000L)
#define B_M5H (B_M4L + 1280000L)
#define B_M5L (B_M5H + 320000L)
#define B_P2H (B_M5L + 320000L)
#define B_P2L (B_P2H + 20480000L)
#define B_P3H (B_P2L + 20480000L)
#define B_P3L (B_P3H + 5120000L)
#define B_P4H (B_P3L + 5120000L)
#define B_P4L (B_P4H + 1280000L)
#define B_P5H (B_P4L + 1280000L)
#define B_P5L (B_P5H + 320000L)
#define B_P6H (B_P5L + 320000L)
#define B_P6L (B_P6H + 86528L)
#define B_POOLH (B_P6L + 86528L)
#define B_POOLL (B_POOLH + 131072L)
#define B_FC1H (B_POOLL + 131072L)
#define B_FC1L (B_FC1H + 524288L)
#define B_WL2H (B_FC1L + 524288L)
#define B_WL2L (B_WL2H + 65536L)
#define B_WL3H (B_WL2L + 65536L)
#define B_WL3L (B_WL3H + 131072L)
#define B_WL4H (B_WL3L + 131072L)
#define B_WL4L (B_WL4H + 262144L)
#define B_WL5H (B_WL4L + 262144L)
#define B_WL5L (B_WL5H + 524288L)
#define B_WFWH (B_WL5L + 524288L)
#define B_WFWL (B_WFWH + 2359296L)
#define B_WP6H (B_WFWL + 2359296L)
#define B_WP6L (B_WP6H + 589824L)
#define B_WRPNH (B_WP6L + 589824L)
#define B_WRPNL (B_WRPNH + 1179648L)
#define B_WFC1H (B_WRPNL + 1179648L)
#define B_WFC1L (B_WFC1H + 262144L)
#define B_WFC2H (B_WFC1L + 262144L)
#define B_WFC2L (B_WFC2H + 1048576L)
#define B_TOTAL (B_WFC2L + 1048576L)

__device__ __align__(16) __nv_bfloat16 g_bscratch[B_TOTAL];

// ---------------- output offsets ----------------
#define OFF_CLS2 0L
#define OFF_CLS3 240000L
#define OFF_CLS4 300000L
#define OFF_CLS5 315000L
#define OFF_CLS6 318750L
#define OFF_REG2 319764L
#define OFF_REG3 1279764L
#define OFF_REG4 1519764L
#define OFF_REG5 1579764L
#define OFF_REG6 1594764L
#define OFF_ROICLS 1598820L
#define OFF_ROIREG 1602916L
#define OFF_ANCH   1619300L

struct ConvParams {
    const float* in;
    const float* w;
    const float* bias;
    float* out;
    int Hin, Win, logCin;
    int Hout, Wout, Cout;
    int M;
    int KW, stride, pad, Ktot, act;
};

struct Conv2Params {
    const __nv_bfloat16* aHi;
    const __nv_bfloat16* aLo;
    const __nv_bfloat16* wHi;
    const __nv_bfloat16* wLo;
    const float* bias;
    float* out;
    __nv_bfloat16* outHi;
    __nv_bfloat16* outLo;
    int Hin, Win, logCin;
    int Hout, Wout, Cout;
    int M;
    int KW, stride, pad, Ktot, act;
};

__device__ __forceinline__ void split_store(__nv_bfloat16* hi, __nv_bfloat16* lo, float4 v) {
    __nv_bfloat16 h0 = __float2bfloat16_rn(v.x);
    __nv_bfloat16 h1 = __float2bfloat16_rn(v.y);
    __nv_bfloat16 h2 = __float2bfloat16_rn(v.z);
    __nv_bfloat16 h3 = __float2bfloat16_rn(v.w);
    __nv_bfloat16 l0 = __float2bfloat16_rn(v.x - __bfloat162float(h0));
    __nv_bfloat16 l1 = __float2bfloat16_rn(v.y - __bfloat162float(h1));
    __nv_bfloat16 l2 = __float2bfloat16_rn(v.z - __bfloat162float(h2));
    __nv_bfloat16 l3 = __float2bfloat16_rn(v.w - __bfloat162float(h3));
    reinterpret_cast<__nv_bfloat162*>(hi)[0] = __nv_bfloat162(h0, h1);
    reinterpret_cast<__nv_bfloat162*>(hi)[1] = __nv_bfloat162(h2, h3);
    reinterpret_cast<__nv_bfloat162*>(lo)[0] = __nv_bfloat162(l0, l1);
    reinterpret_cast<__nv_bfloat162*>(lo)[1] = __nv_bfloat162(l2, l3);
}

__global__ void cvt_split(const float* src, __nv_bfloat16* hi, __nv_bfloat16* lo, int n4) {
    int base = blockIdx.x * (blockDim.x * 4) + threadIdx.x;
#pragma unroll
    for (int q = 0; q < 4; q++) {
        int i = base + q * 256;
        if (i < n4) {
            float4 v = reinterpret_cast<const float4*>(src)[i];
            split_store(hi + (long)i * 4, lo + (long)i * 4, v);
        }
    }
}

// issue one 16-k stage of cp.async loads
__device__ __forceinline__ void issue_stage(
    const Conv2Params& p, int kb, int st,
    __nv_bfloat16* AsH, __nv_bfloat16* AsL,
    __nv_bfloat16* BsH, __nv_bfloat16* BsL,
    long aBase, bool am_ok, int aoh, int aow,
    int arow, int kseg, int krow, int cseg, int n0)
{
    int k0 = kb + kseg;
    int tap = k0 >> p.logCin;
    int ci = k0 & ((1 << p.logCin) - 1);
    int dy = tap / p.KW;
    int dx = tap - dy * p.KW;
    int ih = aoh * p.stride + dy - p.pad;
    int iw = aow * p.stride + dx - p.pad;
    bool ok = am_ok && (unsigned)ih < (unsigned)p.Hin && (unsigned)iw < (unsigned)p.Win;
    size_t zf = ok ? 0 : 16;
    long src = ok ? (aBase + (((long)ih * p.Win + iw) << p.logCin) + ci) : 0;
    __pipeline_memcpy_async(AsH + st * A_ST_ELEM + arow * A_STR + kseg, p.aHi + src, 16, zf);
    __pipeline_memcpy_async(AsL + st * A_ST_ELEM + arow * A_STR + kseg, p.aLo + src, 16, zf);
    long wsrc = (long)(kb + krow) * p.Cout + n0 + cseg;
    __pipeline_memcpy_async(BsH + st * B_ST_ELEM + krow * B_STR + cseg, p.wHi + wsrc, 16, (size_t)0);
    __pipeline_memcpy_async(BsL + st * B_ST_ELEM + krow * B_STR + cseg, p.wLo + wsrc, 16, (size_t)0);
}

__global__ __launch_bounds__(256, 2) void conv_wmma2(Conv2Params p) {
    extern __shared__ __nv_bfloat16 smem[];
    __nv_bfloat16* AsH = smem;
    __nv_bfloat16* AsL = smem + NSTAGE * A_ST_ELEM;
    __nv_bfloat16* BsH = smem + 2 * NSTAGE * A_ST_ELEM;
    __nv_bfloat16* BsL = smem + 2 * NSTAGE * A_ST_ELEM + NSTAGE * B_ST_ELEM;

    const int tid = threadIdx.x;
    const int lane = tid & 31;
    const int warp = tid >> 5;
    const int wm = warp >> 2;
    const int wn = warp & 3;
    const int m0 = blockIdx.x * 128;
    const int n0 = blockIdx.y * 128;

    const int arow = tid >> 1;
    const int kseg = (tid & 1) << 3;
    const int krow = tid >> 4;
    const int cseg = (tid & 15) << 3;

    const int am = m0 + arow;
    const bool am_ok = am < p.M;
    int aoh = 0;
    int aow = 0;
    long aBase = 0;
    if (am_ok) {
        int hw = p.Hout * p.Wout;
        int an = am / hw;
        int r = am - an * hw;
        aoh = r / p.Wout;
        aow = r - aoh * p.Wout;
        aBase = ((long)an * p.Hin * p.Win) << p.logCin;
    }

    wmma::fragment<wmma::accumulator, 16, 16, 16, float> acc[4][2];
#pragma unroll
    for (int mt = 0; mt < 4; mt++) {
#pragma unroll
        for (int nt = 0; nt < 2; nt++) {
            wmma::fill_fragment(acc[mt][nt], 0.0f);
        }
    }

    const int nK = p.Ktot >> 4;

#pragma unroll
    for (int s = 0; s < NSTAGE - 1; s++) {
        if (s < nK) {
            issue_stage(p, s << 4, s, AsH, AsL, BsH, BsL,
                        aBase, am_ok, aoh, aow, arow, kseg, krow, cseg, n0);
        }
        __pipeline_commit();
    }

    for (int kt = 0; kt < nK; kt++) {
        __pipeline_wait_prior(NSTAGE - 2);
        __syncthreads();

        const int st = kt % NSTAGE;
        const __nv_bfloat16* aH = AsH + st * A_ST_ELEM;
        const __nv_bfloat16* aL = AsL + st * A_ST_ELEM;
        const __nv_bfloat16* bH = BsH + st * B_ST_ELEM;
        const __nv_bfloat16* bL = BsL + st * B_ST_ELEM;

        wmma::fragment<wmma::matrix_b, 16, 16, 16, __nv_bfloat16, wmma::row_major> fBH[2];
        wmma::fragment<wmma::matrix_b, 16, 16, 16, __nv_bfloat16, wmma::row_major> fBL[2];
#pragma unroll
        for (int nt = 0; nt < 2; nt++) {
            int bc = wn * 32 + nt * 16;
            wmma::load_matrix_sync(fBH[nt], bH + bc, B_STR);
            wmma::load_matrix_sync(fBL[nt], bL + bc, B_STR);
        }
#pragma unroll
        for (int mt = 0; mt < 4; mt++) {
            wmma::fragment<wmma::matrix_a, 16, 16, 16, __nv_bfloat16, wmma::row_major> fAH;
            wmma::fragment<wmma::matrix_a, 16, 16, 16, __nv_bfloat16, wmma::row_major> fAL;
            int row = wm * 64 + mt * 16;
            wmma::load_matrix_sync(fAH, aH + row * A_STR, A_STR);
            wmma::load_matrix_sync(fAL, aL + row * A_STR, A_STR);
#pragma unroll
            for (int nt = 0; nt < 2; nt++) {
                wmma::mma_sync(acc[mt][nt], fAH, fBH[nt], acc[mt][nt]);
                wmma::mma_sync(acc[mt][nt], fAH, fBL[nt], acc[mt][nt]);
                wmma::mma_sync(acc[mt][nt], fAL, fBH[nt], acc[mt][nt]);
            }
        }

        int kn = kt + NSTAGE - 1;
        if (kn < nK) {
            issue_stage(p, kn << 4, kn % NSTAGE, AsH, AsL, BsH, BsL,
                        aBase, am_ok, aoh, aow, arow, kseg, krow, cseg, n0);
        }
        __pipeline_commit();
    }

    __syncthreads();

    float* Cs = reinterpret_cast<float*>(smem);
    float* cwarp = Cs + warp * 256;
#pragma unroll
    for (int mt = 0; mt < 4; mt++) {
#pragma unroll
        for (int nt = 0; nt < 2; nt++) {
            wmma::store_matrix_sync(cwarp, acc[mt][nt], 16, wmma::mem_row_major);
            __syncwarp();
#pragma unroll
            for (int e = 0; e < 8; e++) {
                int idx = e * 32 + lane;
                int r = idx >> 4;
                int cc = idx & 15;
                int m = m0 + wm * 64 + mt * 16 + r;
                int n = n0 + wn * 32 + nt * 16 + cc;
                if (m < p.M) {
                    float v = cwarp[idx] + p.bias[n];
                    if (p.act == ACT_RELU) v = fmaxf(v, 0.f);
                    long o = (long)m * p.Cout + n;
                    if (p.out) {
                        p.out[o] = v;
                    }
                    if (p.outHi) {
                        __nv_bfloat16 h = __float2bfloat16_rn(v);
                        p.outHi[o] = h;
                        p.outLo[o] = __float2bfloat16_rn(v - __bfloat162float(h));
                    }
                }
            }
            __syncwarp();
        }
    }
}

// ======================= fp32 fallback GEMM (tiny heads) =======================
__global__ __launch_bounds__(256) void conv_gemm(ConvParams p) {
    __shared__ float As[BKC][BM];
    __shared__ float Bs[BKC][BN];
    const int tid = threadIdx.x;
    const int m0 = blockIdx.x * BM;
    const int n0 = blockIdx.y * BN;

    const int arow = tid >> 1;
    const int kq = (tid & 1) << 2;
    const int am = m0 + arow;
    const bool am_ok = am < p.M;
    int aoh = 0;
    int aow = 0;
    const float* abase = p.in;
    if (am_ok) {
        int hw = p.Hout * p.Wout;
        int an = am / hw;
        int r = am - an * hw;
        aoh = r / p.Wout;
        aow = r - aoh * p.Wout;
        abase = p.in + (((long)an * p.Hin * p.Win) << p.logCin);
    }
    const int brow = tid >> 5;
    const int bcol = (tid & 31) << 2;
    const bool bvec = ((p.Cout & 3) == 0) && (n0 + BN <= p.Cout);
    const int cmask = (1 << p.logCin) - 1;

    float acc[8][8];
#pragma unroll
    for (int i = 0; i < 8; i++) {
#pragma unroll
        for (int j = 0; j < 8; j++) {
            acc[i][j] = 0.f;
        }
    }

    const int ty = tid >> 4;
    const int tx = tid & 15;

    for (int kb = 0; kb < p.Ktot; kb += BKC) {
        float4 av = make_float4(0.f, 0.f, 0.f, 0.f);
        if (am_ok) {
            int k0 = kb + kq;
            int tap = k0 >> p.logCin;
            int ci = k0 & cmask;
            int dy = tap / p.KW;
            int dx = tap - dy * p.KW;
            int ih = aoh * p.stride + dy - p.pad;
            int iw = aow * p.stride + dx - p.pad;
            if ((unsigned)ih < (unsigned)p.Hin && (unsigned)iw < (unsigned)p.Win) {
                av = *reinterpret_cast<const float4*>(
                    abase + (((long)ih * p.Win + iw) << p.logCin) + ci);
            }
        }
        As[kq + 0][arow] = av.x;
        As[kq + 1][arow] = av.y;
        As[kq + 2][arow] = av.z;
        As[kq + 3][arow] = av.w;
        {
            int kB = kb + brow;
            const float* wp = p.w + (long)kB * p.Cout + n0 + bcol;
            float4 bv;
            if (bvec) {
                bv = *reinterpret_cast<const float4*>(wp);
            } else {
                int nb = n0 + bcol;
                bv.x = (nb + 0 < p.Cout) ? wp[0] : 0.f;
                bv.y = (nb + 1 < p.Cout) ? wp[1] : 0.f;
                bv.z = (nb + 2 < p.Cout) ? wp[2] : 0.f;
                bv.w = (nb + 3 < p.Cout) ? wp[3] : 0.f;
            }
            *reinterpret_cast<float4*>(&Bs[brow][bcol]) = bv;
        }
        __syncthreads();
#pragma unroll
        for (int kk = 0; kk < BKC; kk++) {
            float4 a0 = *reinterpret_cast<const float4*>(&As[kk][ty << 3]);
            float4 a1 = *reinterpret_cast<const float4*>(&As[kk][(ty << 3) + 4]);
            float4 b0 = *reinterpret_cast<const float4*>(&Bs[kk][tx << 3]);
            float4 b1 = *reinterpret_cast<const float4*>(&Bs[kk][(tx << 3) + 4]);
            float ra[8] = {a0.x, a0.y, a0.z, a0.w, a1.x, a1.y, a1.z, a1.w};
            float rb[8] = {b0.x, b0.y, b0.z, b0.w, b1.x, b1.y, b1.z, b1.w};
#pragma unroll
            for (int i = 0; i < 8; i++) {
#pragma unroll
                for (int j = 0; j < 8; j++) {
                    acc[i][j] += ra[i] * rb[j];
                }
            }
        }
        __syncthreads();
    }

#pragma unroll
    for (int i = 0; i < 8; i++) {
        int m = m0 + (ty << 3) + i;
        if (m >= p.M) continue;
#pragma unroll
        for (int j = 0; j < 8; j++) {
            int n = n0 + (tx << 3) + j;
            if (n >= p.Cout) continue;
            float v = acc[i][j] + p.bias[n];
            if (p.act == ACT_RELU) v = fmaxf(v, 0.f);
            else if (p.act == ACT_SIG) v = 1.f / (1.f + expf(-v));
            p.out[(long)m * p.Cout + n] = v;
        }
    }
}

// ---------------- fused RPN cls+reg head (Cin=512, Cout 3+12) ----------------
__global__ __launch_bounds__(256) void rpn_head_kernel(
    const float* rbuf, const float* clsw, const float* clsb,
    const float* regw, const float* regb,
    float* outc, float* outr, int M)
{
    __shared__ float wsm[512 * 15];
    __shared__ float bsm[15];
    const int tid = threadIdx.x;
    for (int idx = tid; idx < 512 * 15; idx += 256) {
        int k = idx / 15;
        int j = idx - k * 15;
        wsm[idx] = (j < 3) ? clsw[k * 3 + j] : regw[k * 12 + (j - 3)];
    }
    if (tid < 15) {
        bsm[tid] = (tid < 3) ? clsb[tid] : regb[tid - 3];
    }
    __syncthreads();

    const int lane = tid & 31;
    const int warp = tid >> 5;
    for (long row = (long)blockIdx.x * 8 + warp; row < M; row += (long)gridDim.x * 8) {
        const float* rp = rbuf + row * 512;
        float acc[15];
#pragma unroll
        for (int j = 0; j < 15; j++) {
            acc[j] = 0.f;
        }
#pragma unroll
        for (int i = 0; i < 16; i++) {
            int k = i * 32 + lane;
            float a = rp[k];
            const float* wv = wsm + k * 15;
#pragma unroll
            for (int j = 0; j < 15; j++) {
                acc[j] += a * wv[j];
            }
        }
#pragma unroll
        for (int j = 0; j < 15; j++) {
#pragma unroll
            for (int o = 16; o > 0; o >>= 1) {
                acc[j] += __shfl_down_sync(0xffffffffu, acc[j], o);
            }
        }
        if (lane == 0) {
#pragma unroll
            for (int j = 0; j < 3; j++) {
                float v = acc[j] + bsm[j];
                outc[row * 3 + j] = 1.f / (1.f + expf(-v));
            }
#pragma unroll
            for (int j = 3; j < 15; j++) {
                outr[row * 12 + (j - 3)] = acc[j] + bsm[j];
            }
        }
    }
}

// ---------------- FPN top-down add + bf16 split ----------------
__global__ void up2_add_cvt(float* dst, const float* src,
                            __nv_bfloat16* hi, __nv_bfloat16* lo,
                            int H, int W, int total) {
    int i = blockIdx.x * blockDim.x + threadIdx.x;
    if (i >= total) return;
    int c = i & 255;
    int t = i >> 8;
    int w = t % W;
    t /= W;
    int h = t % H;
    int n = t / H;
    int Hs = H >> 1;
    int Ws = W >> 1;
    float v = dst[i] + src[((((long)n * Hs + (h >> 1)) * Ws + (w >> 1)) << 8) + c];
    dst[i] = v;
    __nv_bfloat16 hb = __float2bfloat16_rn(v);
    hi[i] = hb;
    lo[i] = __float2bfloat16_rn(v - __bfloat162float(hb));
}

// ---------------- roi pool -> bf16 hi/lo ----------------
__global__ void roi_pool_kernel(const float* fm, const float* rois,
                                __nv_bfloat16* hi, __nv_bfloat16* lo) {
    int roi = blockIdx.x;
    int c = threadIdx.x;
    __shared__ int sy0[7], sy1[7], sx0[7], sx1[7];
    __shared__ float swy[7], swx[7];
    __shared__ int svy[7], svx[7];
    if (c == 0) {
        float y1 = rois[roi * 4 + 0] / 50.0f;
        float x1 = rois[roi * 4 + 1] / 50.0f;
        float y2 = rois[roi * 4 + 2] / 50.0f;
        float x2 = rois[roi * 4 + 3] / 50.0f;
        for (int i = 0; i < 7; i++) {
            float ys = y1 * 49.0f + (float)i * ((y2 - y1) * 49.0f / 6.0f);
            float xs = x1 * 49.0f + (float)i * ((x2 - x1) * 49.0f / 6.0f);
            float fy = floorf(ys);
            float fx = floorf(xs);
            int iy0 = min(max((int)fy, 0), 49);
            int ix0 = min(max((int)fx, 0), 49);
            sy0[i] = iy0;
            sy1[i] = min(iy0 + 1, 49);
            sx0[i] = ix0;
            sx1[i] = min(ix0 + 1, 49);
            swy[i] = ys - fy;
            swx[i] = xs - fx;
            svy[i] = (ys >= 0.0f && ys <= 49.0f) ? 1 : 0;
            svx[i] = (xs >= 0.0f && xs <= 49.0f) ? 1 : 0;
        }
    }
    __syncthreads();
    float acc = 0.f;
    for (int iy = 0; iy < 7; iy++) {
        if (!svy[iy]) continue;
        float wy = swy[iy];
        const float* r0 = fm + ((long)sy0[iy] * 50 << 8);
        const float* r1 = fm + ((long)sy1[iy] * 50 << 8);
        for (int ix = 0; ix < 7; ix++) {
            if (!svx[ix]) continue;
            float wx = swx[ix];
            float v00 = r0[(sx0[ix] << 8) + c];
            float v01 = r0[(sx1[ix] << 8) + c];
            float v10 = r1[(sx0[ix] << 8) + c];
            float v11 = r1[(sx1[ix] << 8) + c];
            acc += (1.f - wy) * (1.f - wx) * v00 + (1.f - wy) * wx * v01 +
                   wy * (1.f - wx) * v10 + wy * wx * v11;
        }
    }
    float v = acc * (1.0f / 49.0f);
    __nv_bfloat16 hb = __float2bfloat16_rn(v);
    hi[(roi << 8) + c] = hb;
    lo[(roi << 8) + c] = __float2bfloat16_rn(v - __bfloat162float(hb));
}

__global__ void softmax8_kernel(float* x) {
    int r = blockIdx.x * blockDim.x + threadIdx.x;
    if (r >= 512) return;
    float* p = x + r * 8;
    float m = p[0];
#pragma unroll
    for (int i = 1; i < 8; i++) {
        m = fmaxf(m, p[i]);
    }
    float e[8];
    float s = 0.f;
#pragma unroll
    for (int i = 0; i < 8; i++) {
        e[i] = expf(p[i] - m);
        s += e[i];
    }
    float inv = 1.0f / s;
#pragma unroll
    for (int i = 0; i < 8; i++) {
        p[i] = e[i] * inv;
    }
}

__global__ void anchors_kernel(float* out) {
    int idx = blockIdx.x * blockDim.x + threadIdx.x;
    if (idx >= 159882) return;
    int lvl;
    int a;
    if (idx < 120000)      { lvl = 0; a = idx; }
    else if (idx < 150000) { lvl = 1; a = idx - 120000; }
    else if (idx < 157500) { lvl = 2; a = idx - 150000; }
    else if (idx < 159375) { lvl = 3; a = idx - 157500; }
    else                   { lvl = 4; a = idx - 159375; }
    const int   ws[5]  = {200, 100, 50, 25, 13};
    const float scl[5] = {32.f, 64.f, 128.f, 256.f, 512.f};
    const float st[5]  = {4.f, 8.f, 16.f, 32.f, 64.f};
    const float sq[3]  = {0.70710678118654752f, 1.0f, 1.41421356237309505f};
    int r = a % 3;
    int cell = a / 3;
    int w = ws[lvl];
    int y = cell / w;
    int x = cell - y * w;
    float sx = (float)x * st[lvl];
    float sy = (float)y * st[lvl];
    float s = scl[lvl];
    float hx = s * sq[r] * 0.5f;
    float hy = s / sq[r] * 0.5f;
    out[idx * 4 + 0] = sx - hx;
    out[idx * 4 + 1] = sy - hy;
    out[idx * 4 + 2] = sx + hx;
    out[idx * 4 + 3] = sy + hy;
}

// ---------------- host side ----------------
static void run_cvt(const float* src, __nv_bfloat16* hi, __nv_bfloat16* lo, long n) {
    int n4 = (int)(n >> 2);
    cvt_split<<<(n4 + 1023) / 1024, 256>>>(src, hi, lo, n4);
}

static void run_conv2(const __nv_bfloat16* aH, const __nv_bfloat16* aL,
                      const __nv_bfloat16* wH, const __nv_bfloat16* wL,
                      const float* bias, float* out,
                      __nv_bfloat16* outHi, __nv_bfloat16* outLo,
                      int Nb, int Hin, int Win, int logCin,
                      int Hout, int Wout, int Cout,
                      int KW, int KH, int stride, int pad, int act) {
    cudaFuncSetAttribute(conv_wmma2, cudaFuncAttributeMaxDynamicSharedMemorySize, SMEM_DYN);
    Conv2Params p;
    p.aHi = aH;
    p.aLo = aL;
    p.wHi = wH;
    p.wLo = wL;
    p.bias = bias;
    p.out = out;
    p.outHi = outHi;
    p.outLo = outLo;
    p.Hin = Hin;
    p.Win = Win;
    p.logCin = logCin;
    p.Hout = Hout;
    p.Wout = Wout;
    p.Cout = Cout;
    p.M = Nb * Hout * Wout;
    p.KW = KW;
    p.stride = stride;
    p.pad = pad;
    p.Ktot = (KH * KW) << logCin;
    p.act = act;
    dim3 grid((p.M + 127) / 128, Cout / 128);
    conv_wmma2<<<grid, 256, SMEM_DYN>>>(p);
}

static void run_conv(const float* in, const float* w, const float* b, float* out,
                     int Nb, int Hin, int Win, int logCin,
                     int Hout, int Wout, int Cout,
                     int KW, int KH, int stride, int pad, int act) {
    ConvParams p;
    p.in = in;
    p.w = w;
    p.bias = b;
    p.out = out;
    p.Hin = Hin;
    p.Win = Win;
    p.logCin = logCin;
    p.Hout = Hout;
    p.Wout = Wout;
    p.Cout = Cout;
    p.M = Nb * Hout * Wout;
    p.KW = KW;
    p.stride = stride;
    p.pad = pad;
    p.Ktot = (KH * KW) << logCin;
    p.act = act;
    dim3 grid((p.M + BM - 1) / BM, (Cout + BN - 1) / BN);
    conv_gemm<<<grid, 256>>>(p);
}

extern "C" void kernel_launch(void* const* d_in, const int* in_sizes, int n_in,
                              void* d_out, int out_size) {
    const float* feat2 = (const float*)d_in[0];
    const float* feat3 = (const float*)d_in[1];
    const float* feat4 = (const float*)d_in[2];
    const float* feat5 = (const float*)d_in[3];
    const float* rois  = (const float*)d_in[4];
    const float* lw2 = (const float*)d_in[5];
    const float* lb2 = (const float*)d_in[6];
    const float* lw3 = (const float*)d_in[7];
    const float* lb3 = (const float*)d_in[8];
    const float* lw4 = (const float*)d_in[9];
    const float* lb4 = (const float*)d_in[10];
    const float* lw5 = (const float*)d_in[11];
    const float* lb5 = (const float*)d_in[12];
    const float* fw  = (const float*)d_in[13];
    const float* fb  = (const float*)d_in[14];
    const float* p6w = (const float*)d_in[15];
    const float* p6b = (const float*)d_in[16];
    const float* rpnw = (const float*)d_in[17];
    const float* rpnb = (const float*)d_in[18];
    const float* clsw = (const float*)d_in[19];
    const float* clsb = (const float*)d_in[20];
    const float* regw = (const float*)d_in[21];
    const float* regb = (const float*)d_in[22];
    const float* fc1w = (const float*)d_in[23];
    const float* fc1b = (const float*)d_in[24];
    const float* fc2w = (const float*)d_in[25];
    const float* fc2b = (const float*)d_in[26];
    const float* hclsw = (const float*)d_in[27];
    const float* hclsb = (const float*)d_in[28];
    const float* hregw = (const float*)d_in[29];
    const float* hregb = (const float*)d_in[30];
    float* out = (float*)d_out;

    float* sc = 0;
    cudaGetSymbolAddress((void**)&sc, g_scratch);
    __nv_bfloat16* bs = 0;
    cudaGetSymbolAddress((void**)&bs, g_bscratch);

    float* m2 = sc + SC_M2;
    float* m3 = sc + SC_M3;
    float* m4 = sc + SC_M4;
    float* m5 = sc + SC_M5;
    float* p4 = sc + SC_P4;
    float* rbuf = sc + SC_R;
    float* fc2 = sc + SC_FC2;

    // convert weights + input features to bf16 hi/lo
    run_cvt(lw2, bs + B_WL2H, bs + B_WL2L, 65536L);
    run_cvt(lw3, bs + B_WL3H, bs + B_WL3L, 131072L);
    run_cvt(lw4, bs + B_WL4H, bs + B_WL4L, 262144L);
    run_cvt(lw5, bs + B_WL5H, bs + B_WL5L, 524288L);
    run_cvt(fw,  bs + B_WFWH, bs + B_WFWL, 2359296L);
    run_cvt(p6w, bs + B_WP6H, bs + B_WP6L, 589824L);
    run_cvt(rpnw, bs + B_WRPNH, bs + B_WRPNL, 1179648L);
    run_cvt(fc1w, bs + B_WFC1H, bs + B_WFC1L, 262144L);
    run_cvt(fc2w, bs + B_WFC2H, bs + B_WFC2L, 1048576L);
    run_cvt(feat2, bs + B_F2H, bs + B_F2L, 20480000L);
    run_cvt(feat3, bs + B_F3H, bs + B_F3L, 10240000L);
    run_cvt(feat4, bs + B_F4H, bs + B_F4L, 5120000L);
    run_cvt(feat5, bs + B_F5H, bs + B_F5L, 2560000L);

    // laterals (1x1) + top-down (bf16 split fused into producers)
    run_conv2(bs + B_F5H, bs + B_F5L, bs + B_WL5H, bs + B_WL5L, lb5, m5,
              bs + B_M5H, bs + B_M5L, 2, 25, 25, 11, 25, 25, 256, 1, 1, 1, 0, ACT_NONE);
    run_conv2(bs + B_F4H, bs + B_F4L, bs + B_WL4H, bs + B_WL4L, lb4, m4,
              0, 0, 2, 50, 50, 10, 50, 50, 256, 1, 1, 1, 0, ACT_NONE);
    {
        int tot = 2 * 50 * 50 * 256;
        up2_add_cvt<<<(tot + 255) / 256, 256>>>(m4, m5, bs + B_M4H, bs + B_M4L, 50, 50, tot);
    }
    run_conv2(bs + B_F3H, bs + B_F3L, bs + B_WL3H, bs + B_WL3L, lb3, m3,
              0, 0, 2, 100, 100, 9, 100, 100, 256, 1, 1, 1, 0, ACT_NONE);
    {
        int tot = 2 * 100 * 100 * 256;
        up2_add_cvt<<<(tot + 255) / 256, 256>>>(m3, m4, bs + B_M3H, bs + B_M3L, 100, 100, tot);
    }
    run_conv2(bs + B_F2H, bs + B_F2L, bs + B_WL2H, bs + B_WL2L, lb2, m2,
              0, 0, 2, 200, 200, 8, 200, 200, 256, 1, 1, 1, 0, ACT_NONE);
    {
        int tot = 2 * 200 * 200 * 256;
        up2_add_cvt<<<(tot + 255) / 256, 256>>>(m2, m3, bs + B_M2H, bs + B_M2L, 200, 200, tot);
    }

    // FPN 3x3 smoothing convs (bf16 outputs fused; fp32 only where consumed)
    run_conv2(bs + B_M2H, bs + B_M2L, bs + B_WFWH + 0L * 589824L, bs + B_WFWL + 0L * 589824L,
              fb + 0, 0, bs + B_P2H, bs + B_P2L, 2, 200, 200, 8, 200, 200, 256, 3, 3, 1, 1, ACT_NONE);
    run_conv2(bs + B_M3H, bs + B_M3L, bs + B_WFWH + 1L * 589824L, bs + B_WFWL + 1L * 589824L,
              fb + 256, 0, bs + B_P3H, bs + B_P3L, 2, 100, 100, 8, 100, 100, 256, 3, 3, 1, 1, ACT_NONE);
    run_conv2(bs + B_M4H, bs + B_M4L, bs + B_WFWH + 2L * 589824L, bs + B_WFWL + 2L * 589824L,
              fb + 512, p4, bs + B_P4H, bs + B_P4L, 2, 50, 50, 8, 50, 50, 256, 3, 3, 1, 1, ACT_NONE);
    run_conv2(bs + B_M5H, bs + B_M5L, bs + B_WFWH + 3L * 589824L, bs + B_WFWL + 3L * 589824L,
              fb + 768, 0, bs + B_P5H, bs + B_P5L, 2, 25, 25, 8, 25, 25, 256, 3, 3, 1, 1, ACT_NONE);
    run_conv2(bs + B_P5H, bs + B_P5L, bs + B_WP6H, bs + B_WP6L, p6b, 0,
              bs + B_P6H, bs + B_P6L, 2, 25, 25, 8, 13, 13, 256, 3, 3, 2, 1, ACT_NONE);

    // RPN heads per level: big conv on tensor cores, fused cls+reg head
    struct Lv { long ph; long pl; int H; int W; long co; long ro; };
    Lv lv[5] = {
        {B_P2H, B_P2L, 200, 200, OFF_CLS2, OFF_REG2},
        {B_P3H, B_P3L, 100, 100, OFF_CLS3, OFF_REG3},
        {B_P4H, B_P4L,  50,  50, OFF_CLS4, OFF_REG4},
        {B_P5H, B_P5L,  25,  25, OFF_CLS5, OFF_REG5},
        {B_P6H, B_P6L,  13,  13, OFF_CLS6, OFF_REG6}
    };
    for (int i = 0; i < 5; i++) {
        run_conv2(bs + lv[i].ph, bs + lv[i].pl, bs + B_WRPNH, bs + B_WRPNL, rpnb, rbuf,
                  0, 0, 2, lv[i].H, lv[i].W, 8, lv[i].H, lv[i].W, 512, 3, 3, 1, 1, ACT_RELU);
        int M = 2 * lv[i].H * lv[i].W;
        rpn_head_kernel<<<(M + 7) / 8, 256>>>(rbuf, clsw, clsb, regw, regb,
                                              out + lv[i].co, out + lv[i].ro, M);
    }

    // RoI head
    roi_pool_kernel<<<512, 256>>>(p4, rois, bs + B_POOLH, bs + B_POOLL);
    run_conv2(bs + B_POOLH, bs + B_POOLL, bs + B_WFC1H, bs + B_WFC1L, fc1b, 0,
              bs + B_FC1H, bs + B_FC1L, 1, 512, 1, 8, 512, 1, 1024, 1, 1, 1, 0, ACT_RELU);
    run_conv2(bs + B_FC1H, bs + B_FC1L, bs + B_WFC2H, bs + B_WFC2L, fc2b, fc2,
              0, 0, 1, 512, 1, 10, 512, 1, 1024, 1, 1, 1, 0, ACT_RELU);
    run_conv(fc2, hclsw, hclsb, out + OFF_ROICLS, 1, 512, 1, 10, 512, 1, 8, 1, 1, 1, 0, ACT_NONE);
    softmax8_kernel<<<2, 256>>>(out + OFF_ROICLS);
    run_conv(fc2, hregw, hregb, out + OFF_ROIREG, 1, 512, 1, 10, 512, 1, 32, 1, 1, 1, 0, ACT_NONE);

    // anchors
    anchors_kernel<<<(159882 + 255) / 256, 256>>>(out + OFF_ANCH);
}